// round 11
// baseline (speedup 1.0000x reference)
#include <cuda_runtime.h>
#include <math.h>
#include <stdint.h>

#define B_BATCH 2
#define NPTS    20480
#define MPTS    2048
#define CDIM    256
#define ND      16384
#define NS      512
#define NVIEW   800
#define GTH     0.001f

#define TFPS    256               /* threads per CTA                 */
#define KCTA    4                 /* CTAs per batch                  */
#define QSLOT   3072              /* slots owned per CTA             */
#define PPT     12                /* points per thread               */
#define NP      6                 /* f32x2 pairs per thread          */
#define NVMAX   (KCTA*QSLOT)      /* 12288 total compacted capacity  */

/* output offsets (floats), concatenated in reference return order */
#define O_XYZ   0
#define O_FEAT  (B_BATCH*MPTS*3)                    /* 12288    */
#define O_AFF   (O_FEAT + B_BATCH*MPTS*CDIM)        /* 1060864  */
#define O_VIEW  (O_AFF + B_BATCH*ND)                /* 1093632  */
#define O_GRASP (O_VIEW + B_BATCH*NS*NVIEW)         /* 1912832  */

/* fps smem layout (bytes) */
#define SM_PS    0                          /* float4 ps[NVMAX] (196608B) */
#define SM_WIN   (SM_PS + NVMAX*16)         /* int win[MPTS]    (8192B)   */
#define SM_SCAN  (SM_WIN + MPTS*4)          /* int scan[TFPS]   (1024B)   */
#define SM_AUX   (SM_SCAN + TFPS*4)         /* redW[8] + bciA[2] + pad    */
#define SM_TOTAL (SM_AUX + 16*4)

typedef unsigned long long ull;

__device__ float g_views[NVIEW*3];
__device__ int   g_oi[B_BATCH*NPTS];        /* compacted -> original index */
__device__ float g_cc[B_BATCH*NPTS*3];      /* fallback compacted coords   */
__device__ int   g_fps[B_BATCH*MPTS];       /* FPS-selected original idx   */
__device__ int   g_vind[B_BATCH*NS*3];      /* per-approach best view      */
__device__ ull   g_keys[B_BATCH*2*KCTA];    /* DOUBLE-BUFFERED round keys  */

/* ---------- packed f32x2 helpers (per-lane identical to scalar .rn) ---------- */
__device__ __forceinline__ ull pk2(float a, float b){
    ull r; asm("mov.b64 %0, {%1,%2};" : "=l"(r) : "f"(a), "f"(b)); return r;
}
__device__ __forceinline__ void upk2(ull v, float &a, float &b){
    asm("mov.b64 {%0,%1}, %2;" : "=f"(a), "=f"(b) : "l"(v));
}
__device__ __forceinline__ ull add2(ull a, ull b){
    ull r; asm("add.rn.f32x2 %0, %1, %2;" : "=l"(r) : "l"(a), "l"(b)); return r;
}
__device__ __forceinline__ ull mul2(ull a, ull b){
    ull r; asm("mul.rn.f32x2 %0, %1, %2;" : "=l"(r) : "l"(a), "l"(b)); return r;
}
__device__ __forceinline__ void st_rel_u64(ull* p, ull v){
    asm volatile("st.global.release.gpu.b64 [%0], %1;" :: "l"(p), "l"(v) : "memory");
}
__device__ __forceinline__ ull ld_acq_u64(const ull* p){
    ull v;
    asm volatile("ld.global.acquire.gpu.b64 %0, [%1];" : "=l"(v) : "l"(p) : "memory");
    return v;
}

/* ---------- view templates: fp64 Fibonacci sphere, matches numpy ---------- */
__global__ void views_kernel(){
    const double phi = (sqrt(5.0) - 1.0) * 0.5;
    for (int i = threadIdx.x; i < NVIEW; i += blockDim.x){
        double zi = (2.0 * (double)i + 1.0) / (double)NVIEW - 1.0;
        double r2 = 1.0 - zi * zi; if (r2 < 0.0) r2 = 0.0;
        double r  = sqrt(r2);
        double ang = 2.0 * 3.141592653589793 * (double)i * phi;
        g_views[i*3+0] = (float)(r * cos(ang));
        g_views[i*3+1] = (float)(r * sin(ang));
        g_views[i*3+2] = (float)zi;
    }
}

/* ---------- zero-fill the scatter outputs (128-bit stores) ---------- */
__global__ void zero_kernel(float4* __restrict__ p, size_t n4){
    size_t stride = (size_t)gridDim.x * blockDim.x;
    for (size_t i = (size_t)blockIdx.x * blockDim.x + threadIdx.x; i < n4; i += stride)
        p[i] = make_float4(0.f, 0.f, 0.f, 0.f);
}

/* ---------- generic block argmax for 8 warps (fallback path only) ---------- */
__device__ __forceinline__ int block_argmax8(float bestd, int bestc,
                                             float* redD, int* redC, int* bci, int t){
    #pragma unroll
    for (int off = 16; off > 0; off >>= 1){
        float od = __shfl_down_sync(0xffffffffu, bestd, off);
        int   oc = __shfl_down_sync(0xffffffffu, bestc, off);
        if (od > bestd || (od == bestd && oc < bestc)){ bestd = od; bestc = oc; }
    }
    if ((t & 31) == 0){ redD[t>>5] = bestd; redC[t>>5] = bestc; }
    __syncthreads();
    if (t < 32){
        float bd  = (t < 8) ? redD[t] : -3.3e38f;
        int   bcv = (t < 8) ? redC[t] : 0x7fffffff;
        #pragma unroll
        for (int off = 4; off > 0; off >>= 1){
            float od = __shfl_down_sync(0xffffffffu, bd, off);
            int   oc = __shfl_down_sync(0xffffffffu, bcv, off);
            if (od > bd || (od == bd && oc < bcv)){ bd = od; bcv = oc; }
        }
        if (t == 0) *bci = bcv;
    }
    __syncthreads();
    return *bci;
}

/* ---------- masked FPS: 4 CTAs per batch, double-buffered gmem key exchange ---------- */
__global__ void __launch_bounds__(TFPS, 1)
fps_kernel(const float* __restrict__ xyz, const float* __restrict__ gsc){
    extern __shared__ unsigned char fsm[];
    const int b = blockIdx.x / KCTA;
    const int r = blockIdx.x % KCTA;
    const int t = threadIdx.x;
    const int lane = t & 31;
    const int w = t >> 5;
    const float* X = xyz + (size_t)b * NPTS * 3;
    const float* G = gsc + (size_t)b * NPTS;

    float4*   ps   = (float4*)(fsm + SM_PS);
    int*      win  = (int*)(fsm + SM_WIN);
    int*      scan = (int*)(fsm + SM_SCAN);
    unsigned* redW = (unsigned*)(fsm + SM_AUX);    /* [8]  */
    int*      bciA = (int*)(fsm + SM_AUX) + 8;     /* [2]  */

    /* ---- order-preserving compaction (replicated in every CTA) ---- */
    const int CH = NPTS / TFPS;  /* 80 */
    int base = t * CH;
    int cnt = 0;
    for (int j = 0; j < CH; j++) cnt += (G[base + j] > GTH) ? 1 : 0;
    scan[t] = cnt;
    __syncthreads();
    for (int off = 1; off < TFPS; off <<= 1){
        int v = scan[t];
        int a = (t >= off) ? scan[t - off] : 0;
        __syncthreads();
        scan[t] = v + a;
        __syncthreads();
    }
    int Nv  = scan[TFPS - 1];
    int pos = scan[t] - cnt;
    bool fast = (Nv <= NVMAX);
    for (int j = 0; j < CH; j++){
        int idx = base + j;
        if (G[idx] > GTH){
            float x = X[idx*3+0], y = X[idx*3+1], z = X[idx*3+2];
            if (fast){
                ps[pos] = make_float4(x, y, z, 0.f);
            } else if (r == 0){
                size_t gp = ((size_t)b * NPTS + pos) * 3;
                g_cc[gp] = x; g_cc[gp+1] = y; g_cc[gp+2] = z;
            }
            g_oi[b*NPTS + pos] = idx;   /* identical values from all CTAs */
            pos++;
        }
    }
    if (t == 0){ bciA[0] = 0x7fffffff; bciA[1] = 0x7fffffff; win[0] = 0; }
    __syncthreads();

    if (Nv <= 0){
        if (r == 0)
            for (int m = t; m < MPTS; m += TFPS) g_fps[b*MPTS + m] = 0;
        return;
    }

    if (!fast){
        /* fallback (statistically unreachable): CTA 0 alone, old algorithm */
        if (r != 0) return;
        float* dst  = (float*)ps;
        float* redD = (float*)scan;
        int*   redC = (int*)(redD + 8);
        int*   bci  = redC + 8;
        for (int c = t; c < Nv; c += TFPS) dst[c] = 1e10f;
        if (t == 0) g_fps[b*MPTS] = g_oi[b*NPTS];
        __syncthreads();
        float px = g_cc[(size_t)b*NPTS*3+0];
        float py = g_cc[(size_t)b*NPTS*3+1];
        float pz = g_cc[(size_t)b*NPTS*3+2];
        for (int m = 1; m < MPTS; m++){
            float bestd = -1.0f; int bestc = 0x7fffffff;
            for (int c = t; c < Nv; c += TFPS){
                const float* P = &g_cc[((size_t)b*NPTS + c)*3];
                float dx = __fadd_rn(P[0], -px);
                float dy = __fadd_rn(P[1], -py);
                float dz = __fadd_rn(P[2], -pz);
                float d  = __fadd_rn(__fadd_rn(__fmul_rn(dx,dx), __fmul_rn(dy,dy)),
                                     __fmul_rn(dz,dz));
                float nd = fminf(dst[c], d);
                dst[c] = nd;
                if (nd > bestd){ bestd = nd; bestc = c; }
            }
            int wc = block_argmax8(bestd, bestc, redD, redC, bci, t);
            if (t == 0) g_fps[b*MPTS + m] = g_oi[b*NPTS + wc];
            const float* P = &g_cc[((size_t)b*NPTS + wc)*3];
            px = P[0]; py = P[1]; pz = P[2];
            __syncthreads();
        }
        return;
    }

    /* ================= fast path ================= */
    /* CTA r owns global slots [r*QSLOT, (r+1)*QSLOT); coords replicated.
       Pads mirror global slot 0: their Du tracks slot 0's Du bit-exactly,
       and slot 0's true owner (CTA0,t0,i0) always co-claims c=0, so a pad's
       larger fake slot can never win the min-slot fold.

       Key array is DOUBLE-BUFFERED by round parity: a write to buffer p at
       round m+2 requires passing round m+1's poll, which requires all CTAs
       to have published m+1, which happens only after each consumed all
       round-m keys from buffer p. Tags kill replay/cross-run staleness.   */
    ull Xp[NP], Yp[NP], Zp[NP];
    unsigned Du[PPT];
    #pragma unroll
    for (int p = 0; p < NP; p++){
        int c0 = r*QSLOT + t + (2*p) * TFPS;
        int c1 = c0 + TFPS;
        float4 P0 = ps[(c0 < Nv) ? c0 : 0];
        float4 P1 = ps[(c1 < Nv) ? c1 : 0];
        Xp[p] = pk2(P0.x, P1.x);
        Yp[p] = pk2(P0.y, P1.y);
        Zp[p] = pk2(P0.z, P1.z);
        Du[2*p] = __float_as_uint(1e10f); Du[2*p+1] = __float_as_uint(1e10f);
    }
    ull* kp = &g_keys[b*2*KCTA];
    if (r == 0 && t == 0) g_fps[b*MPTS] = g_oi[b*NPTS];
    float4 P0v = ps[0];
    float px = P0v.x, py = P0v.y, pz = P0v.z;
    int par = 0;

    for (int m = 1; m < MPTS; m++){
        /* ---- region A: distance updates + local max tree ---- */
        ull nx = pk2(-px, -px), ny = pk2(-py, -py), nz = pk2(-pz, -pz);
        unsigned v[NP];
        #pragma unroll
        for (int p = 0; p < NP; p++){
            ull dx = add2(Xp[p], nx);               /* x - px */
            ull dy = add2(Yp[p], ny);
            ull dz = add2(Zp[p], nz);
            ull s  = add2(add2(mul2(dx,dx), mul2(dy,dy)), mul2(dz,dz));
            float d0, d1; upk2(s, d0, d1);
            unsigned n0 = min(Du[2*p],   __float_as_uint(d0));
            unsigned n1 = min(Du[2*p+1], __float_as_uint(d1));
            Du[2*p] = n0; Du[2*p+1] = n1;
            v[p] = max(n0, n1);
        }
        unsigned q0 = max(v[0], v[3]);
        unsigned q1 = max(v[1], v[4]);
        unsigned q2 = max(v[2], v[5]);
        unsigned localmax = max(max(q0, q1), q2);

        unsigned wmax = __reduce_max_sync(0xffffffffu, localmax);
        if (lane == 0) redW[w] = wmax;
        __syncthreads();  /* bar1 */

        unsigned rv = (lane < 8) ? redW[lane] : 0u;
        unsigned bmax = __reduce_max_sync(0xffffffffu, rv);
        if (localmax == bmax){
            int c = 0x7fffffff;
            #pragma unroll
            for (int i = 0; i < PPT; i++)
                if (Du[i] == bmax) c = min(c, r*QSLOT + t + i*TFPS);
            atomicMin(&bciA[par], c);
        }
        if (t == 0) bciA[par ^ 1] = 0x7fffffff;
        __syncthreads();  /* bar2 */

        /* ---- publish CTA key to buffer par, poll all 4 keys of buffer par ---- */
        ull* kb = kp + par*KCTA;
        if (t == 0){
            unsigned lslot = (unsigned)bciA[par];
            ull key = ((ull)(unsigned)m << 52) | ((ull)bmax << 20)
                    | (ull)(0xFFFFFu - lslot);
            st_rel_u64(kb + r, key);
        }
        ull k0, k1, k2, k3;
        unsigned tagv = (unsigned)m;
        do {
            k0 = ld_acq_u64(kb + 0);
            k1 = ld_acq_u64(kb + 1);
            k2 = ld_acq_u64(kb + 2);
            k3 = ld_acq_u64(kb + 3);
        } while ((unsigned)(k0 >> 52) != tagv || (unsigned)(k1 >> 52) != tagv ||
                 (unsigned)(k2 >> 52) != tagv || (unsigned)(k3 >> 52) != tagv);
        ull ka = (k1 > k0) ? k1 : k0;
        ull kc = (k3 > k2) ? k3 : k2;
        ull km = (kc > ka) ? kc : ka;
        int wc = (int)(0xFFFFFu - (unsigned)(km & 0xFFFFFu));

        if (t == 0) win[m] = wc;
        float4 P = ps[wc];
        px = P.x; py = P.y; pz = P.z;
        par ^= 1;
    }

    /* ---- deferred slot -> original-index translation ---- */
    __syncthreads();
    if (r == 0)
        for (int m = t; m < MPTS; m += TFPS)
            g_fps[b*MPTS + m] = g_oi[b*NPTS + win[m]];
}

/* ---------- gather xyz + features by FPS indices ---------- */
__global__ void gather_kernel(const float* __restrict__ xyz, const float* __restrict__ feat,
                              float* __restrict__ oxyz, float* __restrict__ ofeat){
    int m = blockIdx.x, b = blockIdx.y;
    int j = g_fps[b*MPTS + m];
    int c = threadIdx.x;
    ofeat[((size_t)(b*MPTS + m))*CDIM + c] = feat[((size_t)b*NPTS + j)*CDIM + c];
    if (c < 3)
        oxyz[((size_t)(b*MPTS + m))*3 + c] = xyz[((size_t)b*NPTS + j)*3 + c];
}

/* ---------- stage 2: 2-NN affordance (d2 = sn + sq - 2*dot, as written) ---------- */
__global__ void nn_kernel(const float* __restrict__ dense, const float* __restrict__ sparse,
                          const float* __restrict__ scores, float* __restrict__ aff){
    __shared__ float sx[NS], sy[NS], sz[NS], sq[NS], sc[NS];
    __shared__ unsigned char sv[NS];
    int b = blockIdx.y;
    for (int i = threadIdx.x; i < NS; i += blockDim.x){
        float x = sparse[((size_t)b*NS + i)*3+0];
        float y = sparse[((size_t)b*NS + i)*3+1];
        float z = sparse[((size_t)b*NS + i)*3+2];
        sx[i]=x; sy[i]=y; sz[i]=z;
        sq[i] = __fadd_rn(__fadd_rn(__fmul_rn(x,x), __fmul_rn(y,y)), __fmul_rn(z,z));
        sv[i] = (x != 0.f || y != 0.f || z != 0.f) ? 1 : 0;
        sc[i] = scores[b*NS + i];
    }
    __syncthreads();
    int j = blockIdx.x * blockDim.x + threadIdx.x;
    float x = dense[((size_t)b*ND + j)*3+0];
    float y = dense[((size_t)b*ND + j)*3+1];
    float z = dense[((size_t)b*ND + j)*3+2];
    float sn = __fadd_rn(__fadd_rn(__fmul_rn(x,x), __fmul_rn(y,y)), __fmul_rn(z,z));
    float d1 = 3.3e38f, d2 = 3.3e38f; int i1 = 0, i2 = 0;
    for (int i = 0; i < NS; i++){
        float dot = __fadd_rn(__fadd_rn(__fmul_rn(x,sx[i]), __fmul_rn(y,sy[i])),
                              __fmul_rn(z,sz[i]));
        float dd  = sv[i] ? __fadd_rn(__fadd_rn(sn, sq[i]), __fmul_rn(-2.0f, dot)) : 1e10f;
        if (dd < d1){ d2 = d1; i2 = i1; d1 = dd; i1 = i; }
        else if (dd < d2){ d2 = dd; i2 = i; }
    }
    aff[b*ND + j] = __fmul_rn(__fadd_rn(sc[i1], sc[i2]), 0.5f);
}

/* ---------- stage 3a: best view per approach dir (argmax dot, tie->first) ---------- */
__global__ void vmax_kernel(const float* __restrict__ appr){
    int gtid = blockIdx.x * blockDim.x + threadIdx.x;
    int wid  = gtid >> 5;
    int lane = gtid & 31;
    if (wid >= B_BATCH*NS*3) return;
    const float* a = appr + (size_t)wid * 3;
    float ax = a[0], ay = a[1], az = a[2];
    float bm = -3.3e38f; int bv = 0x7fffffff;
    for (int v = lane; v < NVIEW; v += 32){
        float d = __fadd_rn(__fadd_rn(__fmul_rn(ax, g_views[v*3+0]),
                                      __fmul_rn(ay, g_views[v*3+1])),
                            __fmul_rn(az, g_views[v*3+2]));
        if (d > bm){ bm = d; bv = v; }
    }
    #pragma unroll
    for (int off = 16; off > 0; off >>= 1){
        float od = __shfl_down_sync(0xffffffffu, bm, off);
        int   ov = __shfl_down_sync(0xffffffffu, bv, off);
        if (od > bm || (od == bm && ov < bv)){ bm = od; bv = ov; }
    }
    if (lane == 0) g_vind[wid] = bv;
}

/* ---------- stage 3b: scatter (one thread per (b,n); k ascending -> last wins) ---------- */
__global__ void scatter_kernel(const float* __restrict__ sparse,
                               const float* __restrict__ nvs,
                               const float* __restrict__ ngs,
                               float* __restrict__ vs_out,
                               float* __restrict__ gs_out){
    int idx = blockIdx.x * blockDim.x + threadIdx.x;   /* b*NS + n */
    if (idx >= B_BATCH*NS) return;
    const float* sp = sparse + (size_t)idx * 3;
    float vm = (sp[0] != 0.f || sp[1] != 0.f || sp[2] != 0.f) ? 1.f : 0.f;
    for (int k = 0; k < 3; k++){
        int v = g_vind[idx*3 + k];
        vs_out[(size_t)idx*NVIEW + v] = __fmul_rn(nvs[idx*3 + k], vm);
        const float* src = ngs + ((size_t)(idx*3 + k)) * 84;
        float* dst = gs_out + ((size_t)idx*NVIEW + v) * 84;
        for (int j = 0; j < 84; j++) dst[j] = __fmul_rn(src[j], vm);
    }
}

extern "C" void kernel_launch(void* const* d_in, const int* in_sizes, int n_in,
                              void* d_out, int out_size){
    const float* seed_xyz   = (const float*)d_in[0];
    const float* seed_feat  = (const float*)d_in[1];
    const float* graspness  = (const float*)d_in[2];
    const float* dense      = (const float*)d_in[3];
    const float* sparse     = (const float*)d_in[4];
    const float* nscores    = (const float*)d_in[5];
    const float* appr       = (const float*)d_in[6];
    const float* nviewsc    = (const float*)d_in[7];
    const float* ngraspsc   = (const float*)d_in[8];
    float* out = (float*)d_out;

    static cudaStream_t s2;
    static cudaEvent_t  e1, e2;
    static int init_done = 0;
    if (!init_done){
        cudaStreamCreateWithFlags(&s2, cudaStreamNonBlocking);
        cudaEventCreateWithFlags(&e1, cudaEventDisableTiming);
        cudaEventCreateWithFlags(&e2, cudaEventDisableTiming);
        cudaFuncSetAttribute(fps_kernel, cudaFuncAttributeMaxDynamicSharedMemorySize,
                             SM_TOTAL);
        init_done = 1;
    }

    /* fork side stream (graph-capturable fork/join pattern) */
    cudaEventRecord(e1, 0);
    cudaStreamWaitEvent(s2, e1, 0);

    /* side stream: everything independent of FPS (overlaps the long fps kernel) */
    {
        size_t n4 = (size_t)(B_BATCH*NS*NVIEW + B_BATCH*NS*NVIEW*84) / 4;
        zero_kernel<<<2048, 256, 0, s2>>>((float4*)(out + O_VIEW), n4);
    }
    views_kernel<<<1, 256, 0, s2>>>();
    nn_kernel<<<dim3(ND/256, B_BATCH), 256, 0, s2>>>(dense, sparse, nscores, out + O_AFF);

    /* main stream: fps (4 CTAs per batch, double-buffered gmem key lockstep) */
    fps_kernel<<<B_BATCH*KCTA, TFPS, SM_TOTAL>>>(seed_xyz, graspness);

    vmax_kernel<<<(B_BATCH*NS*3*32 + 255)/256, 256, 0, s2>>>(appr);
    scatter_kernel<<<(B_BATCH*NS + 255)/256, 256, 0, s2>>>(sparse, nviewsc, ngraspsc,
                                                           out + O_VIEW, out + O_GRASP);
    cudaEventRecord(e2, s2);

    gather_kernel<<<dim3(MPTS, B_BATCH), CDIM>>>(seed_xyz, seed_feat,
                                                 out + O_XYZ, out + O_FEAT);
    /* join */
    cudaStreamWaitEvent(0, e2, 0);
    (void)in_sizes; (void)n_in; (void)out_size;
}

// round 12
// speedup vs baseline: 2.2016x; 2.2016x over previous
#include <cuda_runtime.h>
#include <math.h>
#include <stdint.h>

#define B_BATCH 2
#define NPTS    20480
#define MPTS    2048
#define CDIM    256
#define ND      16384
#define NS      512
#define NVIEW   800
#define GTH     0.001f

#define TFPS    512
#define PMAX    22                /* points per thread             */
#define NPAIR   11                /* f32x2 pairs per thread        */
#define NVMAX   (TFPS*PMAX)       /* 11264 compacted capacity      */
#define NW      16                /* warps per CTA                 */

/* output offsets (floats), concatenated in reference return order */
#define O_XYZ   0
#define O_FEAT  (B_BATCH*MPTS*3)                    /* 12288    */
#define O_AFF   (O_FEAT + B_BATCH*MPTS*CDIM)        /* 1060864  */
#define O_VIEW  (O_AFF + B_BATCH*ND)                /* 1093632  */
#define O_GRASP (O_VIEW + B_BATCH*NS*NVIEW)         /* 1912832  */

/* fps smem layout (bytes) */
#define SM_PS    0                          /* float4 ps[NVMAX] (180224B) */
#define SM_WIN   (SM_PS + NVMAX*16)         /* int win[MPTS]    (8192B)   */
#define SM_SCAN  (SM_WIN + MPTS*4)          /* int scan[TFPS]   (2048B)   */
#define SM_REDK  (SM_SCAN + TFPS*4)         /* ull keys[2][16]  (256B)    */
#define SM_TOTAL (SM_REDK + 2*NW*8)

typedef unsigned long long ull;

__device__ float g_views[NVIEW*3];
__device__ int   g_oi[B_BATCH*NPTS];     /* compacted -> original index */
__device__ float g_cc[B_BATCH*NPTS*3];   /* fallback compacted coords   */
__device__ int   g_fps[B_BATCH*MPTS];    /* FPS-selected original idx   */
__device__ int   g_vind[B_BATCH*NS*3];   /* per-approach best view      */

/* ---------- packed f32x2 helpers (per-lane identical to scalar .rn) ---------- */
__device__ __forceinline__ ull pk2(float a, float b){
    ull r; asm("mov.b64 %0, {%1,%2};" : "=l"(r) : "f"(a), "f"(b)); return r;
}
__device__ __forceinline__ void upk2(ull v, float &a, float &b){
    asm("mov.b64 {%0,%1}, %2;" : "=f"(a), "=f"(b) : "l"(v));
}
__device__ __forceinline__ ull add2(ull a, ull b){
    ull r; asm("add.rn.f32x2 %0, %1, %2;" : "=l"(r) : "l"(a), "l"(b)); return r;
}
__device__ __forceinline__ ull mul2(ull a, ull b){
    ull r; asm("mul.rn.f32x2 %0, %1, %2;" : "=l"(r) : "l"(a), "l"(b)); return r;
}

/* ---------- view templates: fp64 Fibonacci sphere, matches numpy ---------- */
__global__ void views_kernel(){
    const double phi = (sqrt(5.0) - 1.0) * 0.5;
    for (int i = threadIdx.x; i < NVIEW; i += blockDim.x){
        double zi = (2.0 * (double)i + 1.0) / (double)NVIEW - 1.0;
        double r2 = 1.0 - zi * zi; if (r2 < 0.0) r2 = 0.0;
        double r  = sqrt(r2);
        double ang = 2.0 * 3.141592653589793 * (double)i * phi;
        g_views[i*3+0] = (float)(r * cos(ang));
        g_views[i*3+1] = (float)(r * sin(ang));
        g_views[i*3+2] = (float)zi;
    }
}

/* ---------- zero-fill the scatter outputs (128-bit stores) ---------- */
__global__ void zero_kernel(float4* __restrict__ p, size_t n4){
    size_t stride = (size_t)gridDim.x * blockDim.x;
    for (size_t i = (size_t)blockIdx.x * blockDim.x + threadIdx.x; i < n4; i += stride)
        p[i] = make_float4(0.f, 0.f, 0.f, 0.f);
}

/* ---------- generic block argmax, 16 warps (fallback path only) ---------- */
__device__ __forceinline__ int block_argmax(float bestd, int bestc,
                                            float* redD, int* redC, int* bci, int t){
    #pragma unroll
    for (int off = 16; off > 0; off >>= 1){
        float od = __shfl_down_sync(0xffffffffu, bestd, off);
        int   oc = __shfl_down_sync(0xffffffffu, bestc, off);
        if (od > bestd || (od == bestd && oc < bestc)){ bestd = od; bestc = oc; }
    }
    if ((t & 31) == 0){ redD[t>>5] = bestd; redC[t>>5] = bestc; }
    __syncthreads();
    if (t < 32){
        float bd  = (t < 16) ? redD[t] : -3.3e38f;
        int   bcv = (t < 16) ? redC[t] : 0x7fffffff;
        #pragma unroll
        for (int off = 8; off > 0; off >>= 1){
            float od = __shfl_down_sync(0xffffffffu, bd, off);
            int   oc = __shfl_down_sync(0xffffffffu, bcv, off);
            if (od > bd || (od == bd && oc < bcv)){ bd = od; bcv = oc; }
        }
        if (t == 0) *bci = bcv;
    }
    __syncthreads();
    return *bci;
}

/* ---------- masked FPS: one block per batch, barrier-free smem key tail ---------- */
__global__ void __launch_bounds__(TFPS, 1)
fps_kernel(const float* __restrict__ xyz, const float* __restrict__ gsc){
    extern __shared__ unsigned char fsm[];
    const int b = blockIdx.x;
    const int t = threadIdx.x;
    const int lane = t & 31;
    const int w = t >> 5;
    const float* X = xyz + (size_t)b * NPTS * 3;
    const float* G = gsc + (size_t)b * NPTS;

    float4*       ps   = (float4*)(fsm + SM_PS);
    int*          win  = (int*)(fsm + SM_WIN);
    int*          scan = (int*)(fsm + SM_SCAN);
    volatile ull* volK = (volatile ull*)(fsm + SM_REDK);   /* [2][16] */

    /* ---- order-preserving compaction of graspable points ---- */
    const int CH = NPTS / TFPS;  /* 40 */
    int base = t * CH;
    int cnt = 0;
    for (int j = 0; j < CH; j++) cnt += (G[base + j] > GTH) ? 1 : 0;
    scan[t] = cnt;
    __syncthreads();
    for (int off = 1; off < TFPS; off <<= 1){
        int v = scan[t];
        int a = (t >= off) ? scan[t - off] : 0;
        __syncthreads();
        scan[t] = v + a;
        __syncthreads();
    }
    int Nv  = scan[TFPS - 1];
    int pos = scan[t] - cnt;
    bool fast = (Nv <= NVMAX);
    for (int j = 0; j < CH; j++){
        int idx = base + j;
        if (G[idx] > GTH){
            float x = X[idx*3+0], y = X[idx*3+1], z = X[idx*3+2];
            if (fast){
                ps[pos] = make_float4(x, y, z, 0.f);
            } else {
                size_t gp = ((size_t)b * NPTS + pos) * 3;
                g_cc[gp] = x; g_cc[gp+1] = y; g_cc[gp+2] = z;
            }
            g_oi[b*NPTS + pos] = idx;
            pos++;
        }
    }
    /* seed key buffers with an impossible tag (0xFFF) so round-1 polls can't
       accept garbage from a previous launch's leftover smem                 */
    if (t < 2*NW) volK[t] = (ull)0xFFFu << 52;
    if (t == 0) win[0] = 0;
    __syncthreads();

    if (Nv <= 0){
        for (int m = t; m < MPTS; m += TFPS) g_fps[b*MPTS + m] = 0;
        return;
    }

    if (!fast){
        /* fallback (statistically unreachable): dists in smem, coords global */
        float* dst  = (float*)ps;
        float* redD = (float*)scan;
        int*   redC = (int*)(redD + 16);
        int*   bci  = redC + 16;
        for (int c = t; c < Nv; c += TFPS) dst[c] = 1e10f;
        if (t == 0) g_fps[b*MPTS] = g_oi[b*NPTS];
        __syncthreads();
        float px = g_cc[(size_t)b*NPTS*3+0];
        float py = g_cc[(size_t)b*NPTS*3+1];
        float pz = g_cc[(size_t)b*NPTS*3+2];
        for (int m = 1; m < MPTS; m++){
            float bestd = -1.0f; int bestc = 0x7fffffff;
            for (int c = t; c < Nv; c += TFPS){
                const float* P = &g_cc[((size_t)b*NPTS + c)*3];
                float dx = __fadd_rn(P[0], -px);
                float dy = __fadd_rn(P[1], -py);
                float dz = __fadd_rn(P[2], -pz);
                float d  = __fadd_rn(__fadd_rn(__fmul_rn(dx,dx), __fmul_rn(dy,dy)),
                                     __fmul_rn(dz,dz));
                float nd = fminf(dst[c], d);
                dst[c] = nd;
                if (nd > bestd){ bestd = nd; bestc = c; }
            }
            int wc = block_argmax(bestd, bestc, redD, redC, bci, t);
            if (t == 0) g_fps[b*MPTS + m] = g_oi[b*NPTS + wc];
            const float* P = &g_cc[((size_t)b*NPTS + wc)*3];
            px = P[0]; py = P[1]; pz = P[2];
            __syncthreads();
        }
        return;
    }

    /* ================= fast path ================= */
    /* register-resident points; pads mirror slot 0 (their Du tracks slot 0's
       Du bit-exactly; slot 0's true owner (t=0,i=0) always co-claims slot 0,
       so a pad's larger fake slot can never win the min-slot reduction).
       Key table is double-buffered by round parity: overwrite of buffer p at
       round m+2 requires passing round m+1's poll, which requires all warps'
       m+1 keys, which are published only after their round-m folds consumed
       buffer p. Tags kill stale keys across rounds and graph replays.      */
    ull Xp[NPAIR], Yp[NPAIR], Zp[NPAIR];
    unsigned Du[PMAX];
    #pragma unroll
    for (int p = 0; p < NPAIR; p++){
        int c0 = t + (2*p) * TFPS;
        int c1 = c0 + TFPS;
        float4 P0 = ps[(c0 < Nv) ? c0 : 0];
        float4 P1 = ps[(c1 < Nv) ? c1 : 0];
        Xp[p] = pk2(P0.x, P1.x);
        Yp[p] = pk2(P0.y, P1.y);
        Zp[p] = pk2(P0.z, P1.z);
        Du[2*p] = __float_as_uint(1e10f); Du[2*p+1] = __float_as_uint(1e10f);
    }
    if (t == 0) g_fps[b*MPTS] = g_oi[b*NPTS];
    float4 P0v = ps[0];
    float px = P0v.x, py = P0v.y, pz = P0v.z;
    int par = 0;

    for (int m = 1; m < MPTS; m++){
        /* ---- region A: distance updates + eager TREE argmax ---- */
        ull nx = pk2(-px, -px), ny = pk2(-py, -py), nz = pk2(-pz, -pz);
        unsigned vv[NPAIR]; int ii[NPAIR];
        #pragma unroll
        for (int p = 0; p < NPAIR; p++){
            ull dx = add2(Xp[p], nx);               /* x - px */
            ull dy = add2(Yp[p], ny);
            ull dz = add2(Zp[p], nz);
            ull s  = add2(add2(mul2(dx,dx), mul2(dy,dy)), mul2(dz,dz));
            float d0, d1; upk2(s, d0, d1);
            unsigned n0 = min(Du[2*p],   __float_as_uint(d0));
            unsigned n1 = min(Du[2*p+1], __float_as_uint(d1));
            Du[2*p] = n0; Du[2*p+1] = n1;
            bool h = (n1 > n0);                     /* tie -> lower index */
            vv[p] = h ? n1 : n0;
            ii[p] = 2*p + (h ? 1 : 0);
        }
        /* adjacent-pair merge tree (index-contiguous => exact min-slot ties) */
        #define MRG(va,ia,vb,ib,vo,io) { bool g_ = (vb) > (va); \
            vo = g_ ? (vb) : (va); io = g_ ? (ib) : (ia); }
        unsigned a0,a1,a2,a3,a4, b0,b1,b2, c0v, lmax;
        int      e0,e1,e2,e3,e4, f0,f1,f2, c0i, li;
        MRG(vv[0],ii[0],vv[1],ii[1],a0,e0)
        MRG(vv[2],ii[2],vv[3],ii[3],a1,e1)
        MRG(vv[4],ii[4],vv[5],ii[5],a2,e2)
        MRG(vv[6],ii[6],vv[7],ii[7],a3,e3)
        MRG(vv[8],ii[8],vv[9],ii[9],a4,e4)
        MRG(a0,e0,a1,e1,b0,f0)
        MRG(a2,e2,a3,e3,b1,f1)
        MRG(a4,e4,vv[10],ii[10],b2,f2)
        MRG(b0,f0,b1,f1,c0v,c0i)
        MRG(c0v,c0i,b2,f2,lmax,li)
        #undef MRG

        /* ---- warp key: (max dist, then min slot) ---- */
        unsigned wmax = __reduce_max_sync(0xffffffffu, lmax);
        unsigned cand = (lmax == wmax) ? (unsigned)(t + li*TFPS) : 0xffffffffu;
        unsigned ws   = __reduce_min_sync(0xffffffffu, cand);
        ull tagu = (ull)(unsigned)(m & 0xFFF) << 52;
        if (lane == 0)
            volK[par*NW + w] = tagu | ((ull)wmax << 20) | (ull)(0xFFFFFu ^ ws);

        /* ---- barrier-free poll of all 16 warp keys (this round's buffer) ---- */
        ull k[NW];
        unsigned tagv = (unsigned)(m & 0xFFF);
        bool ok;
        do {
            ok = true;
            #pragma unroll
            for (int i = 0; i < NW; i++){
                k[i] = volK[par*NW + i];
                ok &= ((unsigned)(k[i] >> 52) == tagv);
            }
        } while (!ok);

        /* fold 16 keys: u64 max == (max dist, then min slot) */
        #pragma unroll
        for (int i = 0; i < 8; i++) if (k[i+8] > k[i]) k[i] = k[i+8];
        #pragma unroll
        for (int i = 0; i < 4; i++) if (k[i+4] > k[i]) k[i] = k[i+4];
        if (k[2] > k[0]) k[0] = k[2];
        if (k[3] > k[1]) k[1] = k[3];
        if (k[1] > k[0]) k[0] = k[1];
        int wc = (int)(0xFFFFFu ^ (unsigned)(k[0] & 0xFFFFFu));

        if (t == 0) win[m] = wc;
        float4 P = ps[wc];
        px = P.x; py = P.y; pz = P.z;
        par ^= 1;
    }

    /* ---- deferred slot -> original-index translation ---- */
    __syncthreads();
    for (int m = t; m < MPTS; m += TFPS)
        g_fps[b*MPTS + m] = g_oi[b*NPTS + win[m]];
}

/* ---------- gather xyz + features by FPS indices ---------- */
__global__ void gather_kernel(const float* __restrict__ xyz, const float* __restrict__ feat,
                              float* __restrict__ oxyz, float* __restrict__ ofeat){
    int m = blockIdx.x, b = blockIdx.y;
    int j = g_fps[b*MPTS + m];
    int c = threadIdx.x;
    ofeat[((size_t)(b*MPTS + m))*CDIM + c] = feat[((size_t)b*NPTS + j)*CDIM + c];
    if (c < 3)
        oxyz[((size_t)(b*MPTS + m))*3 + c] = xyz[((size_t)b*NPTS + j)*3 + c];
}

/* ---------- stage 2: 2-NN affordance (d2 = sn + sq - 2*dot, as written) ---------- */
__global__ void nn_kernel(const float* __restrict__ dense, const float* __restrict__ sparse,
                          const float* __restrict__ scores, float* __restrict__ aff){
    __shared__ float sx[NS], sy[NS], sz[NS], sq[NS], sc[NS];
    __shared__ unsigned char sv[NS];
    int b = blockIdx.y;
    for (int i = threadIdx.x; i < NS; i += blockDim.x){
        float x = sparse[((size_t)b*NS + i)*3+0];
        float y = sparse[((size_t)b*NS + i)*3+1];
        float z = sparse[((size_t)b*NS + i)*3+2];
        sx[i]=x; sy[i]=y; sz[i]=z;
        sq[i] = __fadd_rn(__fadd_rn(__fmul_rn(x,x), __fmul_rn(y,y)), __fmul_rn(z,z));
        sv[i] = (x != 0.f || y != 0.f || z != 0.f) ? 1 : 0;
        sc[i] = scores[b*NS + i];
    }
    __syncthreads();
    int j = blockIdx.x * blockDim.x + threadIdx.x;
    float x = dense[((size_t)b*ND + j)*3+0];
    float y = dense[((size_t)b*ND + j)*3+1];
    float z = dense[((size_t)b*ND + j)*3+2];
    float sn = __fadd_rn(__fadd_rn(__fmul_rn(x,x), __fmul_rn(y,y)), __fmul_rn(z,z));
    float d1 = 3.3e38f, d2 = 3.3e38f; int i1 = 0, i2 = 0;
    for (int i = 0; i < NS; i++){
        float dot = __fadd_rn(__fadd_rn(__fmul_rn(x,sx[i]), __fmul_rn(y,sy[i])),
                              __fmul_rn(z,sz[i]));
        float dd  = sv[i] ? __fadd_rn(__fadd_rn(sn, sq[i]), __fmul_rn(-2.0f, dot)) : 1e10f;
        if (dd < d1){ d2 = d1; i2 = i1; d1 = dd; i1 = i; }
        else if (dd < d2){ d2 = dd; i2 = i; }
    }
    aff[b*ND + j] = __fmul_rn(__fadd_rn(sc[i1], sc[i2]), 0.5f);
}

/* ---------- stage 3a: best view per approach dir (argmax dot, tie->first) ---------- */
__global__ void vmax_kernel(const float* __restrict__ appr){
    int gtid = blockIdx.x * blockDim.x + threadIdx.x;
    int wid  = gtid >> 5;
    int lane = gtid & 31;
    if (wid >= B_BATCH*NS*3) return;
    const float* a = appr + (size_t)wid * 3;
    float ax = a[0], ay = a[1], az = a[2];
    float bm = -3.3e38f; int bv = 0x7fffffff;
    for (int v = lane; v < NVIEW; v += 32){
        float d = __fadd_rn(__fadd_rn(__fmul_rn(ax, g_views[v*3+0]),
                                      __fmul_rn(ay, g_views[v*3+1])),
                            __fmul_rn(az, g_views[v*3+2]));
        if (d > bm){ bm = d; bv = v; }
    }
    #pragma unroll
    for (int off = 16; off > 0; off >>= 1){
        float od = __shfl_down_sync(0xffffffffu, bm, off);
        int   ov = __shfl_down_sync(0xffffffffu, bv, off);
        if (od > bm || (od == bm && ov < bv)){ bm = od; bv = ov; }
    }
    if (lane == 0) g_vind[wid] = bv;
}

/* ---------- stage 3b: scatter (one thread per (b,n); k ascending -> last wins) ---------- */
__global__ void scatter_kernel(const float* __restrict__ sparse,
                               const float* __restrict__ nvs,
                               const float* __restrict__ ngs,
                               float* __restrict__ vs_out,
                               float* __restrict__ gs_out){
    int idx = blockIdx.x * blockDim.x + threadIdx.x;   /* b*NS + n */
    if (idx >= B_BATCH*NS) return;
    const float* sp = sparse + (size_t)idx * 3;
    float vm = (sp[0] != 0.f || sp[1] != 0.f || sp[2] != 0.f) ? 1.f : 0.f;
    for (int k = 0; k < 3; k++){
        int v = g_vind[idx*3 + k];
        vs_out[(size_t)idx*NVIEW + v] = __fmul_rn(nvs[idx*3 + k], vm);
        const float* src = ngs + ((size_t)(idx*3 + k)) * 84;
        float* dst = gs_out + ((size_t)idx*NVIEW + v) * 84;
        for (int j = 0; j < 84; j++) dst[j] = __fmul_rn(src[j], vm);
    }
}

extern "C" void kernel_launch(void* const* d_in, const int* in_sizes, int n_in,
                              void* d_out, int out_size){
    const float* seed_xyz   = (const float*)d_in[0];
    const float* seed_feat  = (const float*)d_in[1];
    const float* graspness  = (const float*)d_in[2];
    const float* dense      = (const float*)d_in[3];
    const float* sparse     = (const float*)d_in[4];
    const float* nscores    = (const float*)d_in[5];
    const float* appr       = (const float*)d_in[6];
    const float* nviewsc    = (const float*)d_in[7];
    const float* ngraspsc   = (const float*)d_in[8];
    float* out = (float*)d_out;

    static cudaStream_t s2;
    static cudaEvent_t  e1, e2;
    static int init_done = 0;
    if (!init_done){
        cudaStreamCreateWithFlags(&s2, cudaStreamNonBlocking);
        cudaEventCreateWithFlags(&e1, cudaEventDisableTiming);
        cudaEventCreateWithFlags(&e2, cudaEventDisableTiming);
        cudaFuncSetAttribute(fps_kernel, cudaFuncAttributeMaxDynamicSharedMemorySize,
                             SM_TOTAL);
        init_done = 1;
    }

    /* fork side stream (graph-capturable fork/join pattern) */
    cudaEventRecord(e1, 0);
    cudaStreamWaitEvent(s2, e1, 0);

    /* side stream: everything independent of FPS (overlaps the long fps kernel) */
    {
        size_t n4 = (size_t)(B_BATCH*NS*NVIEW + B_BATCH*NS*NVIEW*84) / 4;
        zero_kernel<<<2048, 256, 0, s2>>>((float4*)(out + O_VIEW), n4);
    }
    views_kernel<<<1, 256, 0, s2>>>();
    nn_kernel<<<dim3(ND/256, B_BATCH), 256, 0, s2>>>(dense, sparse, nscores, out + O_AFF);

    /* main stream: fps (1 block per batch, barrier-free smem key tail) */
    fps_kernel<<<B_BATCH, TFPS, SM_TOTAL>>>(seed_xyz, graspness);

    vmax_kernel<<<(B_BATCH*NS*3*32 + 255)/256, 256, 0, s2>>>(appr);
    scatter_kernel<<<(B_BATCH*NS + 255)/256, 256, 0, s2>>>(sparse, nviewsc, ngraspsc,
                                                           out + O_VIEW, out + O_GRASP);
    cudaEventRecord(e2, s2);

    gather_kernel<<<dim3(MPTS, B_BATCH), CDIM>>>(seed_xyz, seed_feat,
                                                 out + O_XYZ, out + O_FEAT);
    /* join */
    cudaStreamWaitEvent(0, e2, 0);
    (void)in_sizes; (void)n_in; (void)out_size;
}

// round 13
// speedup vs baseline: 3.6888x; 1.6755x over previous
#include <cuda_runtime.h>
#include <math.h>
#include <stdint.h>

#define B_BATCH 2
#define NPTS    20480
#define MPTS    2048
#define CDIM    256
#define ND      16384
#define NS      512
#define NVIEW   800
#define GTH     0.001f

#define TFPS    512
#define PMAX    22                /* points per thread             */
#define NPAIR   11                /* f32x2 pairs per thread        */
#define NVMAX   (TFPS*PMAX)       /* 11264 compacted capacity      */
#define NW      16                /* warps per CTA                 */

/* output offsets (floats), concatenated in reference return order */
#define O_XYZ   0
#define O_FEAT  (B_BATCH*MPTS*3)                    /* 12288    */
#define O_AFF   (O_FEAT + B_BATCH*MPTS*CDIM)        /* 1060864  */
#define O_VIEW  (O_AFF + B_BATCH*ND)                /* 1093632  */
#define O_GRASP (O_VIEW + B_BATCH*NS*NVIEW)         /* 1912832  */

/* fps smem layout (bytes) */
#define SM_PS    0                          /* float4 ps[NVMAX] (180224B) */
#define SM_WIN   (SM_PS + NVMAX*16)         /* int win[MPTS]    (8192B)   */
#define SM_SCAN  (SM_WIN + MPTS*4)          /* int scan[TFPS]   (2048B)   */
#define SM_REDK  (SM_SCAN + TFPS*4)         /* ull redK[2][16]  (256B)    */
#define SM_TOTAL (SM_REDK + 2*NW*8)

typedef unsigned long long ull;

__device__ float g_views[NVIEW*3];
__device__ int   g_oi[B_BATCH*NPTS];     /* compacted -> original index */
__device__ float g_cc[B_BATCH*NPTS*3];   /* fallback compacted coords   */
__device__ int   g_fps[B_BATCH*MPTS];    /* FPS-selected original idx   */
__device__ int   g_vind[B_BATCH*NS*3];   /* per-approach best view      */

/* ---------- packed f32x2 helpers (per-lane identical to scalar .rn) ---------- */
__device__ __forceinline__ ull pk2(float a, float b){
    ull r; asm("mov.b64 %0, {%1,%2};" : "=l"(r) : "f"(a), "f"(b)); return r;
}
__device__ __forceinline__ void upk2(ull v, float &a, float &b){
    asm("mov.b64 {%0,%1}, %2;" : "=f"(a), "=f"(b) : "l"(v));
}
__device__ __forceinline__ ull add2(ull a, ull b){
    ull r; asm("add.rn.f32x2 %0, %1, %2;" : "=l"(r) : "l"(a), "l"(b)); return r;
}
__device__ __forceinline__ ull mul2(ull a, ull b){
    ull r; asm("mul.rn.f32x2 %0, %1, %2;" : "=l"(r) : "l"(a), "l"(b)); return r;
}

/* ---------- view templates: fp64 Fibonacci sphere, matches numpy ---------- */
__global__ void views_kernel(){
    const double phi = (sqrt(5.0) - 1.0) * 0.5;
    for (int i = threadIdx.x; i < NVIEW; i += blockDim.x){
        double zi = (2.0 * (double)i + 1.0) / (double)NVIEW - 1.0;
        double r2 = 1.0 - zi * zi; if (r2 < 0.0) r2 = 0.0;
        double r  = sqrt(r2);
        double ang = 2.0 * 3.141592653589793 * (double)i * phi;
        g_views[i*3+0] = (float)(r * cos(ang));
        g_views[i*3+1] = (float)(r * sin(ang));
        g_views[i*3+2] = (float)zi;
    }
}

/* ---------- zero-fill the scatter outputs (128-bit stores) ---------- */
__global__ void zero_kernel(float4* __restrict__ p, size_t n4){
    size_t stride = (size_t)gridDim.x * blockDim.x;
    for (size_t i = (size_t)blockIdx.x * blockDim.x + threadIdx.x; i < n4; i += stride)
        p[i] = make_float4(0.f, 0.f, 0.f, 0.f);
}

/* ---------- generic block argmax, 16 warps (fallback path only) ---------- */
__device__ __forceinline__ int block_argmax(float bestd, int bestc,
                                            float* redD, int* redC, int* bci, int t){
    #pragma unroll
    for (int off = 16; off > 0; off >>= 1){
        float od = __shfl_down_sync(0xffffffffu, bestd, off);
        int   oc = __shfl_down_sync(0xffffffffu, bestc, off);
        if (od > bestd || (od == bestd && oc < bestc)){ bestd = od; bestc = oc; }
    }
    if ((t & 31) == 0){ redD[t>>5] = bestd; redC[t>>5] = bestc; }
    __syncthreads();
    if (t < 32){
        float bd  = (t < 16) ? redD[t] : -3.3e38f;
        int   bcv = (t < 16) ? redC[t] : 0x7fffffff;
        #pragma unroll
        for (int off = 8; off > 0; off >>= 1){
            float od = __shfl_down_sync(0xffffffffu, bd, off);
            int   oc = __shfl_down_sync(0xffffffffu, bcv, off);
            if (od > bd || (od == bd && oc < bcv)){ bd = od; bcv = oc; }
        }
        if (t == 0) *bci = bcv;
    }
    __syncthreads();
    return *bci;
}

/* ---------- masked FPS: one block per batch, single-barrier key tail ---------- */
__global__ void __launch_bounds__(TFPS, 1)
fps_kernel(const float* __restrict__ xyz, const float* __restrict__ gsc){
    extern __shared__ unsigned char fsm[];
    const int b = blockIdx.x;
    const int t = threadIdx.x;
    const int lane = t & 31;
    const int w = t >> 5;
    const float* X = xyz + (size_t)b * NPTS * 3;
    const float* G = gsc + (size_t)b * NPTS;

    float4* ps   = (float4*)(fsm + SM_PS);
    int*    win  = (int*)(fsm + SM_WIN);
    int*    scan = (int*)(fsm + SM_SCAN);
    ull*    redK = (ull*)(fsm + SM_REDK);     /* [2][16] parity-double-buffered */

    /* ---- order-preserving compaction of graspable points ---- */
    const int CH = NPTS / TFPS;  /* 40 */
    int base = t * CH;
    int cnt = 0;
    for (int j = 0; j < CH; j++) cnt += (G[base + j] > GTH) ? 1 : 0;
    scan[t] = cnt;
    __syncthreads();
    for (int off = 1; off < TFPS; off <<= 1){
        int v = scan[t];
        int a = (t >= off) ? scan[t - off] : 0;
        __syncthreads();
        scan[t] = v + a;
        __syncthreads();
    }
    int Nv  = scan[TFPS - 1];
    int pos = scan[t] - cnt;
    bool fast = (Nv <= NVMAX);
    for (int j = 0; j < CH; j++){
        int idx = base + j;
        if (G[idx] > GTH){
            float x = X[idx*3+0], y = X[idx*3+1], z = X[idx*3+2];
            if (fast){
                ps[pos] = make_float4(x, y, z, 0.f);
            } else {
                size_t gp = ((size_t)b * NPTS + pos) * 3;
                g_cc[gp] = x; g_cc[gp+1] = y; g_cc[gp+2] = z;
            }
            g_oi[b*NPTS + pos] = idx;
            pos++;
        }
    }
    if (t == 0) win[0] = 0;
    __syncthreads();

    if (Nv <= 0){
        for (int m = t; m < MPTS; m += TFPS) g_fps[b*MPTS + m] = 0;
        return;
    }

    if (!fast){
        /* fallback (statistically unreachable): dists in smem, coords global */
        float* dst  = (float*)ps;
        float* redD = (float*)scan;
        int*   redC = (int*)(redD + 16);
        int*   bci  = redC + 16;
        for (int c = t; c < Nv; c += TFPS) dst[c] = 1e10f;
        if (t == 0) g_fps[b*MPTS] = g_oi[b*NPTS];
        __syncthreads();
        float px = g_cc[(size_t)b*NPTS*3+0];
        float py = g_cc[(size_t)b*NPTS*3+1];
        float pz = g_cc[(size_t)b*NPTS*3+2];
        for (int m = 1; m < MPTS; m++){
            float bestd = -1.0f; int bestc = 0x7fffffff;
            for (int c = t; c < Nv; c += TFPS){
                const float* P = &g_cc[((size_t)b*NPTS + c)*3];
                float dx = __fadd_rn(P[0], -px);
                float dy = __fadd_rn(P[1], -py);
                float dz = __fadd_rn(P[2], -pz);
                float d  = __fadd_rn(__fadd_rn(__fmul_rn(dx,dx), __fmul_rn(dy,dy)),
                                     __fmul_rn(dz,dz));
                float nd = fminf(dst[c], d);
                dst[c] = nd;
                if (nd > bestd){ bestd = nd; bestc = c; }
            }
            int wc = block_argmax(bestd, bestc, redD, redC, bci, t);
            if (t == 0) g_fps[b*MPTS + m] = g_oi[b*NPTS + wc];
            const float* P = &g_cc[((size_t)b*NPTS + wc)*3];
            px = P[0]; py = P[1]; pz = P[2];
            __syncthreads();
        }
        return;
    }

    /* ================= fast path ================= */
    /* register-resident points; pads mirror slot 0 (their Du tracks slot 0's
       Du bit-exactly; slot 0's true owner (t=0,pair 0) always co-claims slot
       0, so a pad's larger fake slot can never win the min-slot fold).

       redK is parity-double-buffered: round-m reads of buffer p complete
       before each thread arrives at round-(m+1)'s barrier, and any round-
       (m+2) write to buffer p happens after that barrier => no WAR hazard
       with a single barrier per round.                                     */
    ull Xp[NPAIR], Yp[NPAIR], Zp[NPAIR];
    unsigned Du[PMAX];
    #pragma unroll
    for (int p = 0; p < NPAIR; p++){
        int c0 = t + (2*p) * TFPS;
        int c1 = c0 + TFPS;
        float4 P0 = ps[(c0 < Nv) ? c0 : 0];
        float4 P1 = ps[(c1 < Nv) ? c1 : 0];
        Xp[p] = pk2(P0.x, P1.x);
        Yp[p] = pk2(P0.y, P1.y);
        Zp[p] = pk2(P0.z, P1.z);
        Du[2*p] = __float_as_uint(1e10f); Du[2*p+1] = __float_as_uint(1e10f);
    }
    if (t == 0) g_fps[b*MPTS] = g_oi[b*NPTS];
    float4 P0v = ps[0];
    float px = P0v.x, py = P0v.y, pz = P0v.z;
    int par = 0;

    for (int m = 1; m < MPTS; m++){
        /* ---- region A: distance updates + eager TREE argmax (R12-proven) ---- */
        ull nx = pk2(-px, -px), ny = pk2(-py, -py), nz = pk2(-pz, -pz);
        unsigned vv[NPAIR]; int ii[NPAIR];
        #pragma unroll
        for (int p = 0; p < NPAIR; p++){
            ull dx = add2(Xp[p], nx);               /* x - px */
            ull dy = add2(Yp[p], ny);
            ull dz = add2(Zp[p], nz);
            ull s  = add2(add2(mul2(dx,dx), mul2(dy,dy)), mul2(dz,dz));
            float d0, d1; upk2(s, d0, d1);
            unsigned n0 = min(Du[2*p],   __float_as_uint(d0));
            unsigned n1 = min(Du[2*p+1], __float_as_uint(d1));
            Du[2*p] = n0; Du[2*p+1] = n1;
            bool h = (n1 > n0);                     /* tie -> lower index */
            vv[p] = h ? n1 : n0;
            ii[p] = 2*p + (h ? 1 : 0);
        }
        /* adjacent-pair merge tree (index-contiguous => exact min-slot ties) */
        #define MRG(va,ia,vb,ib,vo,io) { bool g_ = (vb) > (va); \
            vo = g_ ? (vb) : (va); io = g_ ? (ib) : (ia); }
        unsigned a0,a1,a2,a3,a4, b0,b1,b2, c0v, lmax;
        int      e0,e1,e2,e3,e4, f0,f1,f2, c0i, li;
        MRG(vv[0],ii[0],vv[1],ii[1],a0,e0)
        MRG(vv[2],ii[2],vv[3],ii[3],a1,e1)
        MRG(vv[4],ii[4],vv[5],ii[5],a2,e2)
        MRG(vv[6],ii[6],vv[7],ii[7],a3,e3)
        MRG(vv[8],ii[8],vv[9],ii[9],a4,e4)
        MRG(a0,e0,a1,e1,b0,f0)
        MRG(a2,e2,a3,e3,b1,f1)
        MRG(a4,e4,vv[10],ii[10],b2,f2)
        MRG(b0,f0,b1,f1,c0v,c0i)
        MRG(c0v,c0i,b2,f2,lmax,li)
        #undef MRG

        /* ---- warp key: (max dist, then min slot), R5/R7-proven ---- */
        unsigned wmax = __reduce_max_sync(0xffffffffu, lmax);
        unsigned cand = (lmax == wmax) ? (unsigned)(t + li*TFPS) : 0xffffffffu;
        unsigned ws   = __reduce_min_sync(0xffffffffu, cand);
        if (lane == 0)
            redK[par*NW + w] = ((ull)wmax << 32) | (ull)(~ws);

        __syncthreads();                            /* single barrier/round */

        /* ---- fold 16 warp keys: one LDS per lane, two REDUX ---- */
        ull k = (lane < NW) ? redK[par*NW + lane] : 0ULL;
        unsigned hi = (unsigned)(k >> 32);
        unsigned bmax = __reduce_max_sync(0xffffffffu, hi);
        unsigned cl = (hi == bmax) ? (unsigned)k : 0u;
        unsigned wl = __reduce_max_sync(0xffffffffu, cl);
        int wc = (int)(~wl);

        if (t == 0) win[m] = wc;
        float4 P = ps[wc];
        px = P.x; py = P.y; pz = P.z;
        par ^= 1;
    }

    /* ---- deferred slot -> original-index translation ---- */
    __syncthreads();
    for (int m = t; m < MPTS; m += TFPS)
        g_fps[b*MPTS + m] = g_oi[b*NPTS + win[m]];
}

/* ---------- gather xyz + features by FPS indices ---------- */
__global__ void gather_kernel(const float* __restrict__ xyz, const float* __restrict__ feat,
                              float* __restrict__ oxyz, float* __restrict__ ofeat){
    int m = blockIdx.x, b = blockIdx.y;
    int j = g_fps[b*MPTS + m];
    int c = threadIdx.x;
    ofeat[((size_t)(b*MPTS + m))*CDIM + c] = feat[((size_t)b*NPTS + j)*CDIM + c];
    if (c < 3)
        oxyz[((size_t)(b*MPTS + m))*3 + c] = xyz[((size_t)b*NPTS + j)*3 + c];
}

/* ---------- stage 2: 2-NN affordance (d2 = sn + sq - 2*dot, as written) ---------- */
__global__ void nn_kernel(const float* __restrict__ dense, const float* __restrict__ sparse,
                          const float* __restrict__ scores, float* __restrict__ aff){
    __shared__ float sx[NS], sy[NS], sz[NS], sq[NS], sc[NS];
    __shared__ unsigned char sv[NS];
    int b = blockIdx.y;
    for (int i = threadIdx.x; i < NS; i += blockDim.x){
        float x = sparse[((size_t)b*NS + i)*3+0];
        float y = sparse[((size_t)b*NS + i)*3+1];
        float z = sparse[((size_t)b*NS + i)*3+2];
        sx[i]=x; sy[i]=y; sz[i]=z;
        sq[i] = __fadd_rn(__fadd_rn(__fmul_rn(x,x), __fmul_rn(y,y)), __fmul_rn(z,z));
        sv[i] = (x != 0.f || y != 0.f || z != 0.f) ? 1 : 0;
        sc[i] = scores[b*NS + i];
    }
    __syncthreads();
    int j = blockIdx.x * blockDim.x + threadIdx.x;
    float x = dense[((size_t)b*ND + j)*3+0];
    float y = dense[((size_t)b*ND + j)*3+1];
    float z = dense[((size_t)b*ND + j)*3+2];
    float sn = __fadd_rn(__fadd_rn(__fmul_rn(x,x), __fmul_rn(y,y)), __fmul_rn(z,z));
    float d1 = 3.3e38f, d2 = 3.3e38f; int i1 = 0, i2 = 0;
    for (int i = 0; i < NS; i++){
        float dot = __fadd_rn(__fadd_rn(__fmul_rn(x,sx[i]), __fmul_rn(y,sy[i])),
                              __fmul_rn(z,sz[i]));
        float dd  = sv[i] ? __fadd_rn(__fadd_rn(sn, sq[i]), __fmul_rn(-2.0f, dot)) : 1e10f;
        if (dd < d1){ d2 = d1; i2 = i1; d1 = dd; i1 = i; }
        else if (dd < d2){ d2 = dd; i2 = i; }
    }
    aff[b*ND + j] = __fmul_rn(__fadd_rn(sc[i1], sc[i2]), 0.5f);
}

/* ---------- stage 3a: best view per approach dir (argmax dot, tie->first) ---------- */
__global__ void vmax_kernel(const float* __restrict__ appr){
    int gtid = blockIdx.x * blockDim.x + threadIdx.x;
    int wid  = gtid >> 5;
    int lane = gtid & 31;
    if (wid >= B_BATCH*NS*3) return;
    const float* a = appr + (size_t)wid * 3;
    float ax = a[0], ay = a[1], az = a[2];
    float bm = -3.3e38f; int bv = 0x7fffffff;
    for (int v = lane; v < NVIEW; v += 32){
        float d = __fadd_rn(__fadd_rn(__fmul_rn(ax, g_views[v*3+0]),
                                      __fmul_rn(ay, g_views[v*3+1])),
                            __fmul_rn(az, g_views[v*3+2]));
        if (d > bm){ bm = d; bv = v; }
    }
    #pragma unroll
    for (int off = 16; off > 0; off >>= 1){
        float od = __shfl_down_sync(0xffffffffu, bm, off);
        int   ov = __shfl_down_sync(0xffffffffu, bv, off);
        if (od > bm || (od == bm && ov < bv)){ bm = od; bv = ov; }
    }
    if (lane == 0) g_vind[wid] = bv;
}

/* ---------- stage 3b: scatter (one thread per (b,n); k ascending -> last wins) ---------- */
__global__ void scatter_kernel(const float* __restrict__ sparse,
                               const float* __restrict__ nvs,
                               const float* __restrict__ ngs,
                               float* __restrict__ vs_out,
                               float* __restrict__ gs_out){
    int idx = blockIdx.x * blockDim.x + threadIdx.x;   /* b*NS + n */
    if (idx >= B_BATCH*NS) return;
    const float* sp = sparse + (size_t)idx * 3;
    float vm = (sp[0] != 0.f || sp[1] != 0.f || sp[2] != 0.f) ? 1.f : 0.f;
    for (int k = 0; k < 3; k++){
        int v = g_vind[idx*3 + k];
        vs_out[(size_t)idx*NVIEW + v] = __fmul_rn(nvs[idx*3 + k], vm);
        const float* src = ngs + ((size_t)(idx*3 + k)) * 84;
        float* dst = gs_out + ((size_t)idx*NVIEW + v) * 84;
        for (int j = 0; j < 84; j++) dst[j] = __fmul_rn(src[j], vm);
    }
}

extern "C" void kernel_launch(void* const* d_in, const int* in_sizes, int n_in,
                              void* d_out, int out_size){
    const float* seed_xyz   = (const float*)d_in[0];
    const float* seed_feat  = (const float*)d_in[1];
    const float* graspness  = (const float*)d_in[2];
    const float* dense      = (const float*)d_in[3];
    const float* sparse     = (const float*)d_in[4];
    const float* nscores    = (const float*)d_in[5];
    const float* appr       = (const float*)d_in[6];
    const float* nviewsc    = (const float*)d_in[7];
    const float* ngraspsc   = (const float*)d_in[8];
    float* out = (float*)d_out;

    static cudaStream_t s2;
    static cudaEvent_t  e1, e2;
    static int init_done = 0;
    if (!init_done){
        cudaStreamCreateWithFlags(&s2, cudaStreamNonBlocking);
        cudaEventCreateWithFlags(&e1, cudaEventDisableTiming);
        cudaEventCreateWithFlags(&e2, cudaEventDisableTiming);
        cudaFuncSetAttribute(fps_kernel, cudaFuncAttributeMaxDynamicSharedMemorySize,
                             SM_TOTAL);
        init_done = 1;
    }

    /* fork side stream (graph-capturable fork/join pattern) */
    cudaEventRecord(e1, 0);
    cudaStreamWaitEvent(s2, e1, 0);

    /* side stream: everything independent of FPS (overlaps the long fps kernel) */
    {
        size_t n4 = (size_t)(B_BATCH*NS*NVIEW + B_BATCH*NS*NVIEW*84) / 4;
        zero_kernel<<<2048, 256, 0, s2>>>((float4*)(out + O_VIEW), n4);
    }
    views_kernel<<<1, 256, 0, s2>>>();
    nn_kernel<<<dim3(ND/256, B_BATCH), 256, 0, s2>>>(dense, sparse, nscores, out + O_AFF);

    /* main stream: fps (1 block per batch, single-barrier key tail) */
    fps_kernel<<<B_BATCH, TFPS, SM_TOTAL>>>(seed_xyz, graspness);

    vmax_kernel<<<(B_BATCH*NS*3*32 + 255)/256, 256, 0, s2>>>(appr);
    scatter_kernel<<<(B_BATCH*NS + 255)/256, 256, 0, s2>>>(sparse, nviewsc, ngraspsc,
                                                           out + O_VIEW, out + O_GRASP);
    cudaEventRecord(e2, s2);

    gather_kernel<<<dim3(MPTS, B_BATCH), CDIM>>>(seed_xyz, seed_feat,
                                                 out + O_XYZ, out + O_FEAT);
    /* join */
    cudaStreamWaitEvent(0, e2, 0);
    (void)in_sizes; (void)n_in; (void)out_size;
}

// round 14
// speedup vs baseline: 3.6961x; 1.0020x over previous
#include <cuda_runtime.h>
#include <math.h>
#include <stdint.h>

#define B_BATCH 2
#define NPTS    20480
#define MPTS    2048
#define CDIM    256
#define ND      16384
#define NS      512
#define NVIEW   800
#define GTH     0.001f

#define TFPS    512
#define PMAX    22                /* points per thread             */
#define NPAIR   11                /* f32x2 pairs per thread        */
#define NVMAX   (TFPS*PMAX)       /* 11264 compacted capacity      */
#define NW      16                /* warps per CTA                 */

/* output offsets (floats), concatenated in reference return order */
#define O_XYZ   0
#define O_FEAT  (B_BATCH*MPTS*3)                    /* 12288    */
#define O_AFF   (O_FEAT + B_BATCH*MPTS*CDIM)        /* 1060864  */
#define O_VIEW  (O_AFF + B_BATCH*ND)                /* 1093632  */
#define O_GRASP (O_VIEW + B_BATCH*NS*NVIEW)         /* 1912832  */

/* fps smem layout (bytes) */
#define SM_PS    0                          /* float4 ps[NVMAX] (180224B) */
#define SM_WIN   (SM_PS + NVMAX*16)         /* int win[MPTS]    (8192B)   */
#define SM_SCAN  (SM_WIN + MPTS*4)          /* int scan[TFPS]   (2048B)   */
#define SM_REDK  (SM_SCAN + TFPS*4)         /* ull redK[2][16]  (256B)    */
#define SM_TOTAL (SM_REDK + 2*NW*8)

typedef unsigned long long ull;

__device__ float g_views[NVIEW*3];
__device__ int   g_oi[B_BATCH*NPTS];     /* compacted -> original index */
__device__ float g_cc[B_BATCH*NPTS*3];   /* fallback compacted coords   */
__device__ int   g_fps[B_BATCH*MPTS];    /* FPS-selected original idx   */
__device__ int   g_vind[B_BATCH*NS*3];   /* per-approach best view      */

/* ---------- packed f32x2 helpers (per-lane identical to scalar .rn) ---------- */
__device__ __forceinline__ ull pk2(float a, float b){
    ull r; asm("mov.b64 %0, {%1,%2};" : "=l"(r) : "f"(a), "f"(b)); return r;
}
__device__ __forceinline__ void upk2(ull v, float &a, float &b){
    asm("mov.b64 {%0,%1}, %2;" : "=f"(a), "=f"(b) : "l"(v));
}
__device__ __forceinline__ ull add2(ull a, ull b){
    ull r; asm("add.rn.f32x2 %0, %1, %2;" : "=l"(r) : "l"(a), "l"(b)); return r;
}
__device__ __forceinline__ ull mul2(ull a, ull b){
    ull r; asm("mul.rn.f32x2 %0, %1, %2;" : "=l"(r) : "l"(a), "l"(b)); return r;
}

/* ---------- view templates: fp64 Fibonacci sphere, matches numpy ---------- */
__global__ void views_kernel(){
    const double phi = (sqrt(5.0) - 1.0) * 0.5;
    for (int i = threadIdx.x; i < NVIEW; i += blockDim.x){
        double zi = (2.0 * (double)i + 1.0) / (double)NVIEW - 1.0;
        double r2 = 1.0 - zi * zi; if (r2 < 0.0) r2 = 0.0;
        double r  = sqrt(r2);
        double ang = 2.0 * 3.141592653589793 * (double)i * phi;
        g_views[i*3+0] = (float)(r * cos(ang));
        g_views[i*3+1] = (float)(r * sin(ang));
        g_views[i*3+2] = (float)zi;
    }
}

/* ---------- zero-fill the scatter outputs (128-bit stores) ---------- */
__global__ void zero_kernel(float4* __restrict__ p, size_t n4){
    size_t stride = (size_t)gridDim.x * blockDim.x;
    for (size_t i = (size_t)blockIdx.x * blockDim.x + threadIdx.x; i < n4; i += stride)
        p[i] = make_float4(0.f, 0.f, 0.f, 0.f);
}

/* ---------- generic block argmax, 16 warps (fallback path only) ---------- */
__device__ __forceinline__ int block_argmax(float bestd, int bestc,
                                            float* redD, int* redC, int* bci, int t){
    #pragma unroll
    for (int off = 16; off > 0; off >>= 1){
        float od = __shfl_down_sync(0xffffffffu, bestd, off);
        int   oc = __shfl_down_sync(0xffffffffu, bestc, off);
        if (od > bestd || (od == bestd && oc < bestc)){ bestd = od; bestc = oc; }
    }
    if ((t & 31) == 0){ redD[t>>5] = bestd; redC[t>>5] = bestc; }
    __syncthreads();
    if (t < 32){
        float bd  = (t < 16) ? redD[t] : -3.3e38f;
        int   bcv = (t < 16) ? redC[t] : 0x7fffffff;
        #pragma unroll
        for (int off = 8; off > 0; off >>= 1){
            float od = __shfl_down_sync(0xffffffffu, bd, off);
            int   oc = __shfl_down_sync(0xffffffffu, bcv, off);
            if (od > bd || (od == bd && oc < bcv)){ bd = od; bcv = oc; }
        }
        if (t == 0) *bci = bcv;
    }
    __syncthreads();
    return *bci;
}

/* ---------- masked FPS: one block per batch ---------- */
/* R9 region A (value-only max tree) + warp-scope lazy rescan + single barrier */
__global__ void __launch_bounds__(TFPS, 1)
fps_kernel(const float* __restrict__ xyz, const float* __restrict__ gsc){
    extern __shared__ unsigned char fsm[];
    const int b = blockIdx.x;
    const int t = threadIdx.x;
    const int lane = t & 31;
    const int w = t >> 5;
    const float* X = xyz + (size_t)b * NPTS * 3;
    const float* G = gsc + (size_t)b * NPTS;

    float4* ps   = (float4*)(fsm + SM_PS);
    int*    win  = (int*)(fsm + SM_WIN);
    int*    scan = (int*)(fsm + SM_SCAN);
    ull*    redK = (ull*)(fsm + SM_REDK);     /* [2][16] parity-double-buffered */

    /* ---- order-preserving compaction of graspable points ---- */
    const int CH = NPTS / TFPS;  /* 40 */
    int base = t * CH;
    int cnt = 0;
    for (int j = 0; j < CH; j++) cnt += (G[base + j] > GTH) ? 1 : 0;
    scan[t] = cnt;
    __syncthreads();
    for (int off = 1; off < TFPS; off <<= 1){
        int v = scan[t];
        int a = (t >= off) ? scan[t - off] : 0;
        __syncthreads();
        scan[t] = v + a;
        __syncthreads();
    }
    int Nv  = scan[TFPS - 1];
    int pos = scan[t] - cnt;
    bool fast = (Nv <= NVMAX);
    for (int j = 0; j < CH; j++){
        int idx = base + j;
        if (G[idx] > GTH){
            float x = X[idx*3+0], y = X[idx*3+1], z = X[idx*3+2];
            if (fast){
                ps[pos] = make_float4(x, y, z, 0.f);
            } else {
                size_t gp = ((size_t)b * NPTS + pos) * 3;
                g_cc[gp] = x; g_cc[gp+1] = y; g_cc[gp+2] = z;
            }
            g_oi[b*NPTS + pos] = idx;
            pos++;
        }
    }
    if (t == 0) win[0] = 0;
    __syncthreads();

    if (Nv <= 0){
        for (int m = t; m < MPTS; m += TFPS) g_fps[b*MPTS + m] = 0;
        return;
    }

    if (!fast){
        /* fallback (statistically unreachable): dists in smem, coords global */
        float* dst  = (float*)ps;
        float* redD = (float*)scan;
        int*   redC = (int*)(redD + 16);
        int*   bci  = redC + 16;
        for (int c = t; c < Nv; c += TFPS) dst[c] = 1e10f;
        if (t == 0) g_fps[b*MPTS] = g_oi[b*NPTS];
        __syncthreads();
        float px = g_cc[(size_t)b*NPTS*3+0];
        float py = g_cc[(size_t)b*NPTS*3+1];
        float pz = g_cc[(size_t)b*NPTS*3+2];
        for (int m = 1; m < MPTS; m++){
            float bestd = -1.0f; int bestc = 0x7fffffff;
            for (int c = t; c < Nv; c += TFPS){
                const float* P = &g_cc[((size_t)b*NPTS + c)*3];
                float dx = __fadd_rn(P[0], -px);
                float dy = __fadd_rn(P[1], -py);
                float dz = __fadd_rn(P[2], -pz);
                float d  = __fadd_rn(__fadd_rn(__fmul_rn(dx,dx), __fmul_rn(dy,dy)),
                                     __fmul_rn(dz,dz));
                float nd = fminf(dst[c], d);
                dst[c] = nd;
                if (nd > bestd){ bestd = nd; bestc = c; }
            }
            int wc = block_argmax(bestd, bestc, redD, redC, bci, t);
            if (t == 0) g_fps[b*MPTS + m] = g_oi[b*NPTS + wc];
            const float* P = &g_cc[((size_t)b*NPTS + wc)*3];
            px = P[0]; py = P[1]; pz = P[2];
            __syncthreads();
        }
        return;
    }

    /* ================= fast path ================= */
    /* register-resident points; pads mirror slot 0 (their Du tracks slot 0's
       Du bit-exactly; slot 0's true owner (t=0,pair 0) always co-claims slot
       0, so a pad's larger fake slot can never win the min-slot fold).

       redK is parity-double-buffered: round-m reads of buffer p complete
       before each thread arrives at round-(m+1)'s barrier, and any round-
       (m+2) write to buffer p happens after that barrier => no WAR hazard
       with a single barrier per round.                                     */
    ull Xp[NPAIR], Yp[NPAIR], Zp[NPAIR];
    unsigned Du[PMAX];
    #pragma unroll
    for (int p = 0; p < NPAIR; p++){
        int c0 = t + (2*p) * TFPS;
        int c1 = c0 + TFPS;
        float4 P0 = ps[(c0 < Nv) ? c0 : 0];
        float4 P1 = ps[(c1 < Nv) ? c1 : 0];
        Xp[p] = pk2(P0.x, P1.x);
        Yp[p] = pk2(P0.y, P1.y);
        Zp[p] = pk2(P0.z, P1.z);
        Du[2*p] = __float_as_uint(1e10f); Du[2*p+1] = __float_as_uint(1e10f);
    }
    if (t == 0) g_fps[b*MPTS] = g_oi[b*NPTS];
    float4 P0v = ps[0];
    float px = P0v.x, py = P0v.y, pz = P0v.z;
    int par = 0;

    for (int m = 1; m < MPTS; m++){
        /* ---- region A: distance updates + value-only max tree (R9) ---- */
        ull nx = pk2(-px, -px), ny = pk2(-py, -py), nz = pk2(-pz, -pz);
        unsigned v[NPAIR];
        #pragma unroll
        for (int p = 0; p < NPAIR; p++){
            ull dx = add2(Xp[p], nx);               /* x - px */
            ull dy = add2(Yp[p], ny);
            ull dz = add2(Zp[p], nz);
            ull s  = add2(add2(mul2(dx,dx), mul2(dy,dy)), mul2(dz,dz));
            float d0, d1; upk2(s, d0, d1);
            unsigned n0 = min(Du[2*p],   __float_as_uint(d0));
            unsigned n1 = min(Du[2*p+1], __float_as_uint(d1));
            Du[2*p] = n0; Du[2*p+1] = n1;
            v[p] = max(n0, n1);
        }
        unsigned m0 = max(v[0], v[1]);
        unsigned m1 = max(v[2], v[3]);
        unsigned m2 = max(v[4], v[5]);
        unsigned m3 = max(v[6], v[7]);
        unsigned m4 = max(v[8], v[9]);
        unsigned q0 = max(m0, m1);
        unsigned q1 = max(m2, m3);
        unsigned q2 = max(m4, v[10]);
        unsigned localmax = max(max(q0, q1), q2);

        /* ---- warp max, then LAZY warp-scope rescan (predicated, 1 thr/warp) ---- */
        unsigned wmax = __reduce_max_sync(0xffffffffu, localmax);
        unsigned cand = 0xffffffffu;
        if (localmax == wmax){
            int c = 0x7fffffff;
            #pragma unroll
            for (int i = 0; i < PMAX; i++)
                if (Du[i] == wmax) c = min(c, t + i*TFPS);
            cand = (unsigned)c;
        }
        unsigned ws = __reduce_min_sync(0xffffffffu, cand);
        if (lane == 0)
            redK[par*NW + w] = ((ull)wmax << 32) | (ull)(~ws);

        __syncthreads();                            /* single barrier/round */

        /* ---- fold 16 warp keys: one LDS per lane, two REDUX (R13) ---- */
        ull k = (lane < NW) ? redK[par*NW + lane] : 0ULL;
        unsigned hi = (unsigned)(k >> 32);
        unsigned bmax = __reduce_max_sync(0xffffffffu, hi);
        unsigned cl = (hi == bmax) ? (unsigned)k : 0u;
        unsigned wl = __reduce_max_sync(0xffffffffu, cl);
        int wc = (int)(~wl);

        if (t == 0) win[m] = wc;
        float4 P = ps[wc];
        px = P.x; py = P.y; pz = P.z;
        par ^= 1;
    }

    /* ---- deferred slot -> original-index translation ---- */
    __syncthreads();
    for (int m = t; m < MPTS; m += TFPS)
        g_fps[b*MPTS + m] = g_oi[b*NPTS + win[m]];
}

/* ---------- gather xyz + features by FPS indices ---------- */
__global__ void gather_kernel(const float* __restrict__ xyz, const float* __restrict__ feat,
                              float* __restrict__ oxyz, float* __restrict__ ofeat){
    int m = blockIdx.x, b = blockIdx.y;
    int j = g_fps[b*MPTS + m];
    int c = threadIdx.x;
    ofeat[((size_t)(b*MPTS + m))*CDIM + c] = feat[((size_t)b*NPTS + j)*CDIM + c];
    if (c < 3)
        oxyz[((size_t)(b*MPTS + m))*3 + c] = xyz[((size_t)b*NPTS + j)*3 + c];
}

/* ---------- stage 2: 2-NN affordance (d2 = sn + sq - 2*dot, as written) ---------- */
__global__ void nn_kernel(const float* __restrict__ dense, const float* __restrict__ sparse,
                          const float* __restrict__ scores, float* __restrict__ aff){
    __shared__ float sx[NS], sy[NS], sz[NS], sq[NS], sc[NS];
    __shared__ unsigned char sv[NS];
    int b = blockIdx.y;
    for (int i = threadIdx.x; i < NS; i += blockDim.x){
        float x = sparse[((size_t)b*NS + i)*3+0];
        float y = sparse[((size_t)b*NS + i)*3+1];
        float z = sparse[((size_t)b*NS + i)*3+2];
        sx[i]=x; sy[i]=y; sz[i]=z;
        sq[i] = __fadd_rn(__fadd_rn(__fmul_rn(x,x), __fmul_rn(y,y)), __fmul_rn(z,z));
        sv[i] = (x != 0.f || y != 0.f || z != 0.f) ? 1 : 0;
        sc[i] = scores[b*NS + i];
    }
    __syncthreads();
    int j = blockIdx.x * blockDim.x + threadIdx.x;
    float x = dense[((size_t)b*ND + j)*3+0];
    float y = dense[((size_t)b*ND + j)*3+1];
    float z = dense[((size_t)b*ND + j)*3+2];
    float sn = __fadd_rn(__fadd_rn(__fmul_rn(x,x), __fmul_rn(y,y)), __fmul_rn(z,z));
    float d1 = 3.3e38f, d2 = 3.3e38f; int i1 = 0, i2 = 0;
    for (int i = 0; i < NS; i++){
        float dot = __fadd_rn(__fadd_rn(__fmul_rn(x,sx[i]), __fmul_rn(y,sy[i])),
                              __fmul_rn(z,sz[i]));
        float dd  = sv[i] ? __fadd_rn(__fadd_rn(sn, sq[i]), __fmul_rn(-2.0f, dot)) : 1e10f;
        if (dd < d1){ d2 = d1; i2 = i1; d1 = dd; i1 = i; }
        else if (dd < d2){ d2 = dd; i2 = i; }
    }
    aff[b*ND + j] = __fmul_rn(__fadd_rn(sc[i1], sc[i2]), 0.5f);
}

/* ---------- stage 3a: best view per approach dir (argmax dot, tie->first) ---------- */
__global__ void vmax_kernel(const float* __restrict__ appr){
    int gtid = blockIdx.x * blockDim.x + threadIdx.x;
    int wid  = gtid >> 5;
    int lane = gtid & 31;
    if (wid >= B_BATCH*NS*3) return;
    const float* a = appr + (size_t)wid * 3;
    float ax = a[0], ay = a[1], az = a[2];
    float bm = -3.3e38f; int bv = 0x7fffffff;
    for (int v = lane; v < NVIEW; v += 32){
        float d = __fadd_rn(__fadd_rn(__fmul_rn(ax, g_views[v*3+0]),
                                      __fmul_rn(ay, g_views[v*3+1])),
                            __fmul_rn(az, g_views[v*3+2]));
        if (d > bm){ bm = d; bv = v; }
    }
    #pragma unroll
    for (int off = 16; off > 0; off >>= 1){
        float od = __shfl_down_sync(0xffffffffu, bm, off);
        int   ov = __shfl_down_sync(0xffffffffu, bv, off);
        if (od > bm || (od == bm && ov < bv)){ bm = od; bv = ov; }
    }
    if (lane == 0) g_vind[wid] = bv;
}

/* ---------- stage 3b: scatter (one thread per (b,n); k ascending -> last wins) ---------- */
__global__ void scatter_kernel(const float* __restrict__ sparse,
                               const float* __restrict__ nvs,
                               const float* __restrict__ ngs,
                               float* __restrict__ vs_out,
                               float* __restrict__ gs_out){
    int idx = blockIdx.x * blockDim.x + threadIdx.x;   /* b*NS + n */
    if (idx >= B_BATCH*NS) return;
    const float* sp = sparse + (size_t)idx * 3;
    float vm = (sp[0] != 0.f || sp[1] != 0.f || sp[2] != 0.f) ? 1.f : 0.f;
    for (int k = 0; k < 3; k++){
        int v = g_vind[idx*3 + k];
        vs_out[(size_t)idx*NVIEW + v] = __fmul_rn(nvs[idx*3 + k], vm);
        const float* src = ngs + ((size_t)(idx*3 + k)) * 84;
        float* dst = gs_out + ((size_t)idx*NVIEW + v) * 84;
        for (int j = 0; j < 84; j++) dst[j] = __fmul_rn(src[j], vm);
    }
}

extern "C" void kernel_launch(void* const* d_in, const int* in_sizes, int n_in,
                              void* d_out, int out_size){
    const float* seed_xyz   = (const float*)d_in[0];
    const float* seed_feat  = (const float*)d_in[1];
    const float* graspness  = (const float*)d_in[2];
    const float* dense      = (const float*)d_in[3];
    const float* sparse     = (const float*)d_in[4];
    const float* nscores    = (const float*)d_in[5];
    const float* appr       = (const float*)d_in[6];
    const float* nviewsc    = (const float*)d_in[7];
    const float* ngraspsc   = (const float*)d_in[8];
    float* out = (float*)d_out;

    static cudaStream_t s2;
    static cudaEvent_t  e1, e2;
    static int init_done = 0;
    if (!init_done){
        cudaStreamCreateWithFlags(&s2, cudaStreamNonBlocking);
        cudaEventCreateWithFlags(&e1, cudaEventDisableTiming);
        cudaEventCreateWithFlags(&e2, cudaEventDisableTiming);
        cudaFuncSetAttribute(fps_kernel, cudaFuncAttributeMaxDynamicSharedMemorySize,
                             SM_TOTAL);
        init_done = 1;
    }

    /* fork side stream (graph-capturable fork/join pattern) */
    cudaEventRecord(e1, 0);
    cudaStreamWaitEvent(s2, e1, 0);

    /* side stream: everything independent of FPS (overlaps the long fps kernel) */
    {
        size_t n4 = (size_t)(B_BATCH*NS*NVIEW + B_BATCH*NS*NVIEW*84) / 4;
        zero_kernel<<<2048, 256, 0, s2>>>((float4*)(out + O_VIEW), n4);
    }
    views_kernel<<<1, 256, 0, s2>>>();
    nn_kernel<<<dim3(ND/256, B_BATCH), 256, 0, s2>>>(dense, sparse, nscores, out + O_AFF);

    /* main stream: fps (1 block per batch, warp-lazy rescan, single barrier) */
    fps_kernel<<<B_BATCH, TFPS, SM_TOTAL>>>(seed_xyz, graspness);

    vmax_kernel<<<(B_BATCH*NS*3*32 + 255)/256, 256, 0, s2>>>(appr);
    scatter_kernel<<<(B_BATCH*NS + 255)/256, 256, 0, s2>>>(sparse, nviewsc, ngraspsc,
                                                           out + O_VIEW, out + O_GRASP);
    cudaEventRecord(e2, s2);

    gather_kernel<<<dim3(MPTS, B_BATCH), CDIM>>>(seed_xyz, seed_feat,
                                                 out + O_XYZ, out + O_FEAT);
    /* join */
    cudaStreamWaitEvent(0, e2, 0);
    (void)in_sizes; (void)n_in; (void)out_size;
}

// round 15
// speedup vs baseline: 4.1880x; 1.1331x over previous
#include <cuda_runtime.h>
#include <math.h>
#include <stdint.h>

#define B_BATCH 2
#define NPTS    20480
#define MPTS    2048
#define CDIM    256
#define ND      16384
#define NS      512
#define NVIEW   800
#define GTH     0.001f

#define TFPS    512
#define PMAX    22                /* points per thread             */
#define NPAIR   11                /* f32x2 pairs per thread        */
#define NVMAX   (TFPS*PMAX)       /* 11264 compacted capacity      */
#define NW      16                /* warps per CTA                 */

/* output offsets (floats), concatenated in reference return order */
#define O_XYZ   0
#define O_FEAT  (B_BATCH*MPTS*3)                    /* 12288    */
#define O_AFF   (O_FEAT + B_BATCH*MPTS*CDIM)        /* 1060864  */
#define O_VIEW  (O_AFF + B_BATCH*ND)                /* 1093632  */
#define O_GRASP (O_VIEW + B_BATCH*NS*NVIEW)         /* 1912832  */

/* fps smem layout (bytes) */
#define SM_PS    0                          /* float4 ps[NVMAX] (180224B) */
#define SM_WIN   (SM_PS + NVMAX*16)         /* int win[MPTS]    (8192B)   */
#define SM_SCAN  (SM_WIN + MPTS*4)          /* int scan[TFPS]   (2048B)   */
#define SM_AUX   (SM_SCAN + TFPS*4)         /* redW[16] + bciA[2] + pad   */
#define SM_TOTAL (SM_AUX + 32*4)

typedef unsigned long long ull;

__device__ float g_views[NVIEW*3];
__device__ int   g_oi[B_BATCH*NPTS];     /* compacted -> original index */
__device__ float g_cc[B_BATCH*NPTS*3];   /* fallback compacted coords   */
__device__ int   g_fps[B_BATCH*MPTS];    /* FPS-selected original idx   */
__device__ int   g_vind[B_BATCH*NS*3];   /* per-approach best view      */

/* ---------- packed f32x2 helpers (per-lane identical to scalar .rn) ---------- */
__device__ __forceinline__ ull pk2(float a, float b){
    ull r; asm("mov.b64 %0, {%1,%2};" : "=l"(r) : "f"(a), "f"(b)); return r;
}
__device__ __forceinline__ void upk2(ull v, float &a, float &b){
    asm("mov.b64 {%0,%1}, %2;" : "=f"(a), "=f"(b) : "l"(v));
}
__device__ __forceinline__ ull add2(ull a, ull b){
    ull r; asm("add.rn.f32x2 %0, %1, %2;" : "=l"(r) : "l"(a), "l"(b)); return r;
}
__device__ __forceinline__ ull mul2(ull a, ull b){
    ull r; asm("mul.rn.f32x2 %0, %1, %2;" : "=l"(r) : "l"(a), "l"(b)); return r;
}

/* ---------- view templates: fp64 Fibonacci sphere, matches numpy ---------- */
__global__ void views_kernel(){
    const double phi = (sqrt(5.0) - 1.0) * 0.5;
    for (int i = threadIdx.x; i < NVIEW; i += blockDim.x){
        double zi = (2.0 * (double)i + 1.0) / (double)NVIEW - 1.0;
        double r2 = 1.0 - zi * zi; if (r2 < 0.0) r2 = 0.0;
        double r  = sqrt(r2);
        double ang = 2.0 * 3.141592653589793 * (double)i * phi;
        g_views[i*3+0] = (float)(r * cos(ang));
        g_views[i*3+1] = (float)(r * sin(ang));
        g_views[i*3+2] = (float)zi;
    }
}

/* ---------- zero-fill the scatter outputs (128-bit stores) ---------- */
__global__ void zero_kernel(float4* __restrict__ p, size_t n4){
    size_t stride = (size_t)gridDim.x * blockDim.x;
    for (size_t i = (size_t)blockIdx.x * blockDim.x + threadIdx.x; i < n4; i += stride)
        p[i] = make_float4(0.f, 0.f, 0.f, 0.f);
}

/* ---------- generic block argmax, 16 warps (fallback path only) ---------- */
__device__ __forceinline__ int block_argmax(float bestd, int bestc,
                                            float* redD, int* redC, int* bci, int t){
    #pragma unroll
    for (int off = 16; off > 0; off >>= 1){
        float od = __shfl_down_sync(0xffffffffu, bestd, off);
        int   oc = __shfl_down_sync(0xffffffffu, bestc, off);
        if (od > bestd || (od == bestd && oc < bestc)){ bestd = od; bestc = oc; }
    }
    if ((t & 31) == 0){ redD[t>>5] = bestd; redC[t>>5] = bestc; }
    __syncthreads();
    if (t < 32){
        float bd  = (t < 16) ? redD[t] : -3.3e38f;
        int   bcv = (t < 16) ? redC[t] : 0x7fffffff;
        #pragma unroll
        for (int off = 8; off > 0; off >>= 1){
            float od = __shfl_down_sync(0xffffffffu, bd, off);
            int   oc = __shfl_down_sync(0xffffffffu, bcv, off);
            if (od > bd || (od == bd && oc < bcv)){ bd = od; bcv = oc; }
        }
        if (t == 0) *bci = bcv;
    }
    __syncthreads();
    return *bci;
}

/* ---------- masked FPS: one block per batch, R3 two-barrier structure ---------- */
/* change vs R3/R9: lazy rescan is a select+min TREE (latency ~30 cyc) instead
   of a 22-deep dependent predicated-min chain (~90 cyc) on the bar2 path.   */
__global__ void __launch_bounds__(TFPS, 1)
fps_kernel(const float* __restrict__ xyz, const float* __restrict__ gsc){
    extern __shared__ unsigned char fsm[];
    const int b = blockIdx.x;
    const int t = threadIdx.x;
    const int lane = t & 31;
    const int w = t >> 5;
    const float* X = xyz + (size_t)b * NPTS * 3;
    const float* G = gsc + (size_t)b * NPTS;

    float4*   ps   = (float4*)(fsm + SM_PS);
    int*      win  = (int*)(fsm + SM_WIN);
    int*      scan = (int*)(fsm + SM_SCAN);
    unsigned* redW = (unsigned*)(fsm + SM_AUX);    /* [16] */
    int*      bciA = (int*)(fsm + SM_AUX) + 16;    /* [2]  */

    /* ---- order-preserving compaction of graspable points ---- */
    const int CH = NPTS / TFPS;  /* 40 */
    int base = t * CH;
    int cnt = 0;
    for (int j = 0; j < CH; j++) cnt += (G[base + j] > GTH) ? 1 : 0;
    scan[t] = cnt;
    __syncthreads();
    for (int off = 1; off < TFPS; off <<= 1){
        int v = scan[t];
        int a = (t >= off) ? scan[t - off] : 0;
        __syncthreads();
        scan[t] = v + a;
        __syncthreads();
    }
    int Nv  = scan[TFPS - 1];
    int pos = scan[t] - cnt;
    bool fast = (Nv <= NVMAX);
    for (int j = 0; j < CH; j++){
        int idx = base + j;
        if (G[idx] > GTH){
            float x = X[idx*3+0], y = X[idx*3+1], z = X[idx*3+2];
            if (fast){
                ps[pos] = make_float4(x, y, z, 0.f);
            } else {
                size_t gp = ((size_t)b * NPTS + pos) * 3;
                g_cc[gp] = x; g_cc[gp+1] = y; g_cc[gp+2] = z;
            }
            g_oi[b*NPTS + pos] = idx;
            pos++;
        }
    }
    if (t == 0){ bciA[0] = 0x7fffffff; bciA[1] = 0x7fffffff; win[0] = 0; }
    __syncthreads();

    if (Nv <= 0){
        for (int m = t; m < MPTS; m += TFPS) g_fps[b*MPTS + m] = 0;
        return;
    }

    if (!fast){
        /* fallback (statistically unreachable): dists in smem, coords global */
        float* dst  = (float*)ps;
        float* redD = (float*)scan;
        int*   redC = (int*)(redD + 16);
        int*   bci  = redC + 16;
        for (int c = t; c < Nv; c += TFPS) dst[c] = 1e10f;
        if (t == 0) g_fps[b*MPTS] = g_oi[b*NPTS];
        __syncthreads();
        float px = g_cc[(size_t)b*NPTS*3+0];
        float py = g_cc[(size_t)b*NPTS*3+1];
        float pz = g_cc[(size_t)b*NPTS*3+2];
        for (int m = 1; m < MPTS; m++){
            float bestd = -1.0f; int bestc = 0x7fffffff;
            for (int c = t; c < Nv; c += TFPS){
                const float* P = &g_cc[((size_t)b*NPTS + c)*3];
                float dx = __fadd_rn(P[0], -px);
                float dy = __fadd_rn(P[1], -py);
                float dz = __fadd_rn(P[2], -pz);
                float d  = __fadd_rn(__fadd_rn(__fmul_rn(dx,dx), __fmul_rn(dy,dy)),
                                     __fmul_rn(dz,dz));
                float nd = fminf(dst[c], d);
                dst[c] = nd;
                if (nd > bestd){ bestd = nd; bestc = c; }
            }
            int wc = block_argmax(bestd, bestc, redD, redC, bci, t);
            if (t == 0) g_fps[b*MPTS + m] = g_oi[b*NPTS + wc];
            const float* P = &g_cc[((size_t)b*NPTS + wc)*3];
            px = P[0]; py = P[1]; pz = P[2];
            __syncthreads();
        }
        return;
    }

    /* ================= fast path ================= */
    /* register-resident points; pads mirror slot 0 (their Du tracks slot 0's
       Du bit-exactly; slot 0's true owner (t=0,pair 0) always co-claims slot
       0, so a pad's larger fake slot can never win the atomicMin).          */
    ull Xp[NPAIR], Yp[NPAIR], Zp[NPAIR];
    unsigned Du[PMAX];
    #pragma unroll
    for (int p = 0; p < NPAIR; p++){
        int c0 = t + (2*p) * TFPS;
        int c1 = c0 + TFPS;
        float4 P0 = ps[(c0 < Nv) ? c0 : 0];
        float4 P1 = ps[(c1 < Nv) ? c1 : 0];
        Xp[p] = pk2(P0.x, P1.x);
        Yp[p] = pk2(P0.y, P1.y);
        Zp[p] = pk2(P0.z, P1.z);
        Du[2*p] = __float_as_uint(1e10f); Du[2*p+1] = __float_as_uint(1e10f);
    }
    if (t == 0) g_fps[b*MPTS] = g_oi[b*NPTS];
    float4 P0v = ps[0];
    float px = P0v.x, py = P0v.y, pz = P0v.z;
    int par = 0;

    for (int m = 1; m < MPTS; m++){
        /* ---- region A: distance updates + value-only max tree (R3/R9) ---- */
        ull nx = pk2(-px, -px), ny = pk2(-py, -py), nz = pk2(-pz, -pz);
        unsigned v[NPAIR];
        #pragma unroll
        for (int p = 0; p < NPAIR; p++){
            ull dx = add2(Xp[p], nx);               /* x - px */
            ull dy = add2(Yp[p], ny);
            ull dz = add2(Zp[p], nz);
            ull s  = add2(add2(mul2(dx,dx), mul2(dy,dy)), mul2(dz,dz));
            float d0, d1; upk2(s, d0, d1);
            unsigned n0 = min(Du[2*p],   __float_as_uint(d0));
            unsigned n1 = min(Du[2*p+1], __float_as_uint(d1));
            Du[2*p] = n0; Du[2*p+1] = n1;
            v[p] = max(n0, n1);
        }
        unsigned m0 = max(v[0], v[1]);
        unsigned m1 = max(v[2], v[3]);
        unsigned m2 = max(v[4], v[5]);
        unsigned m3 = max(v[6], v[7]);
        unsigned m4 = max(v[8], v[9]);
        unsigned q0 = max(m0, m1);
        unsigned q1 = max(m2, m3);
        unsigned q2 = max(m4, v[10]);
        unsigned localmax = max(max(q0, q1), q2);

        unsigned wmax = __reduce_max_sync(0xffffffffu, localmax);
        if (lane == 0) redW[w] = wmax;
        __syncthreads();  /* bar1 */

        unsigned rv = (lane < NW) ? redW[lane] : 0u;
        unsigned bmax = __reduce_max_sync(0xffffffffu, rv);
        if (t == 0) bciA[par ^ 1] = 0x7fffffff;   /* independent; issues early */

        if (localmax == bmax){
            /* select+min TREE: slot = t + i*TFPS increases with i, so the
               tree min == first match == reference tie-break. Latency ~30
               cyc vs ~90 for the old dependent predicated-min chain.      */
            int e[NPAIR];
            #pragma unroll
            for (int p = 0; p < NPAIR; p++){
                int s0 = (Du[2*p]   == bmax) ? (t + (2*p)*TFPS)   : 0x7fffffff;
                int s1 = (Du[2*p+1] == bmax) ? (t + (2*p+1)*TFPS) : 0x7fffffff;
                e[p] = min(s0, s1);
            }
            int f0 = min(e[0], e[1]);
            int f1 = min(e[2], e[3]);
            int f2 = min(e[4], e[5]);
            int f3 = min(e[6], e[7]);
            int f4 = min(e[8], e[9]);
            int g0 = min(f0, f1);
            int g1 = min(f2, f3);
            int g2 = min(f4, e[10]);
            int c  = min(min(g0, g1), g2);
            atomicMin(&bciA[par], c);
        }
        __syncthreads();  /* bar2 */

        int wc = bciA[par];
        if (t == 0) win[m] = wc;
        float4 P = ps[wc];
        px = P.x; py = P.y; pz = P.z;
        par ^= 1;
    }

    /* ---- deferred slot -> original-index translation ---- */
    __syncthreads();
    for (int m = t; m < MPTS; m += TFPS)
        g_fps[b*MPTS + m] = g_oi[b*NPTS + win[m]];
}

/* ---------- gather xyz + features by FPS indices ---------- */
__global__ void gather_kernel(const float* __restrict__ xyz, const float* __restrict__ feat,
                              float* __restrict__ oxyz, float* __restrict__ ofeat){
    int m = blockIdx.x, b = blockIdx.y;
    int j = g_fps[b*MPTS + m];
    int c = threadIdx.x;
    ofeat[((size_t)(b*MPTS + m))*CDIM + c] = feat[((size_t)b*NPTS + j)*CDIM + c];
    if (c < 3)
        oxyz[((size_t)(b*MPTS + m))*3 + c] = xyz[((size_t)b*NPTS + j)*3 + c];
}

/* ---------- stage 2: 2-NN affordance (d2 = sn + sq - 2*dot, as written) ---------- */
__global__ void nn_kernel(const float* __restrict__ dense, const float* __restrict__ sparse,
                          const float* __restrict__ scores, float* __restrict__ aff){
    __shared__ float sx[NS], sy[NS], sz[NS], sq[NS], sc[NS];
    __shared__ unsigned char sv[NS];
    int b = blockIdx.y;
    for (int i = threadIdx.x; i < NS; i += blockDim.x){
        float x = sparse[((size_t)b*NS + i)*3+0];
        float y = sparse[((size_t)b*NS + i)*3+1];
        float z = sparse[((size_t)b*NS + i)*3+2];
        sx[i]=x; sy[i]=y; sz[i]=z;
        sq[i] = __fadd_rn(__fadd_rn(__fmul_rn(x,x), __fmul_rn(y,y)), __fmul_rn(z,z));
        sv[i] = (x != 0.f || y != 0.f || z != 0.f) ? 1 : 0;
        sc[i] = scores[b*NS + i];
    }
    __syncthreads();
    int j = blockIdx.x * blockDim.x + threadIdx.x;
    float x = dense[((size_t)b*ND + j)*3+0];
    float y = dense[((size_t)b*ND + j)*3+1];
    float z = dense[((size_t)b*ND + j)*3+2];
    float sn = __fadd_rn(__fadd_rn(__fmul_rn(x,x), __fmul_rn(y,y)), __fmul_rn(z,z));
    float d1 = 3.3e38f, d2 = 3.3e38f; int i1 = 0, i2 = 0;
    for (int i = 0; i < NS; i++){
        float dot = __fadd_rn(__fadd_rn(__fmul_rn(x,sx[i]), __fmul_rn(y,sy[i])),
                              __fmul_rn(z,sz[i]));
        float dd  = sv[i] ? __fadd_rn(__fadd_rn(sn, sq[i]), __fmul_rn(-2.0f, dot)) : 1e10f;
        if (dd < d1){ d2 = d1; i2 = i1; d1 = dd; i1 = i; }
        else if (dd < d2){ d2 = dd; i2 = i; }
    }
    aff[b*ND + j] = __fmul_rn(__fadd_rn(sc[i1], sc[i2]), 0.5f);
}

/* ---------- stage 3a: best view per approach dir (argmax dot, tie->first) ---------- */
__global__ void vmax_kernel(const float* __restrict__ appr){
    int gtid = blockIdx.x * blockDim.x + threadIdx.x;
    int wid  = gtid >> 5;
    int lane = gtid & 31;
    if (wid >= B_BATCH*NS*3) return;
    const float* a = appr + (size_t)wid * 3;
    float ax = a[0], ay = a[1], az = a[2];
    float bm = -3.3e38f; int bv = 0x7fffffff;
    for (int v = lane; v < NVIEW; v += 32){
        float d = __fadd_rn(__fadd_rn(__fmul_rn(ax, g_views[v*3+0]),
                                      __fmul_rn(ay, g_views[v*3+1])),
                            __fmul_rn(az, g_views[v*3+2]));
        if (d > bm){ bm = d; bv = v; }
    }
    #pragma unroll
    for (int off = 16; off > 0; off >>= 1){
        float od = __shfl_down_sync(0xffffffffu, bm, off);
        int   ov = __shfl_down_sync(0xffffffffu, bv, off);
        if (od > bm || (od == bm && ov < bv)){ bm = od; bv = ov; }
    }
    if (lane == 0) g_vind[wid] = bv;
}

/* ---------- stage 3b: scatter (one thread per (b,n); k ascending -> last wins) ---------- */
__global__ void scatter_kernel(const float* __restrict__ sparse,
                               const float* __restrict__ nvs,
                               const float* __restrict__ ngs,
                               float* __restrict__ vs_out,
                               float* __restrict__ gs_out){
    int idx = blockIdx.x * blockDim.x + threadIdx.x;   /* b*NS + n */
    if (idx >= B_BATCH*NS) return;
    const float* sp = sparse + (size_t)idx * 3;
    float vm = (sp[0] != 0.f || sp[1] != 0.f || sp[2] != 0.f) ? 1.f : 0.f;
    for (int k = 0; k < 3; k++){
        int v = g_vind[idx*3 + k];
        vs_out[(size_t)idx*NVIEW + v] = __fmul_rn(nvs[idx*3 + k], vm);
        const float* src = ngs + ((size_t)(idx*3 + k)) * 84;
        float* dst = gs_out + ((size_t)idx*NVIEW + v) * 84;
        for (int j = 0; j < 84; j++) dst[j] = __fmul_rn(src[j], vm);
    }
}

extern "C" void kernel_launch(void* const* d_in, const int* in_sizes, int n_in,
                              void* d_out, int out_size){
    const float* seed_xyz   = (const float*)d_in[0];
    const float* seed_feat  = (const float*)d_in[1];
    const float* graspness  = (const float*)d_in[2];
    const float* dense      = (const float*)d_in[3];
    const float* sparse     = (const float*)d_in[4];
    const float* nscores    = (const float*)d_in[5];
    const float* appr       = (const float*)d_in[6];
    const float* nviewsc    = (const float*)d_in[7];
    const float* ngraspsc   = (const float*)d_in[8];
    float* out = (float*)d_out;

    static cudaStream_t s2;
    static cudaEvent_t  e1, e2;
    static int init_done = 0;
    if (!init_done){
        cudaStreamCreateWithFlags(&s2, cudaStreamNonBlocking);
        cudaEventCreateWithFlags(&e1, cudaEventDisableTiming);
        cudaEventCreateWithFlags(&e2, cudaEventDisableTiming);
        cudaFuncSetAttribute(fps_kernel, cudaFuncAttributeMaxDynamicSharedMemorySize,
                             SM_TOTAL);
        init_done = 1;
    }

    /* fork side stream (graph-capturable fork/join pattern) */
    cudaEventRecord(e1, 0);
    cudaStreamWaitEvent(s2, e1, 0);

    /* side stream: everything independent of FPS (overlaps the long fps kernel) */
    {
        size_t n4 = (size_t)(B_BATCH*NS*NVIEW + B_BATCH*NS*NVIEW*84) / 4;
        zero_kernel<<<2048, 256, 0, s2>>>((float4*)(out + O_VIEW), n4);
    }
    views_kernel<<<1, 256, 0, s2>>>();
    nn_kernel<<<dim3(ND/256, B_BATCH), 256, 0, s2>>>(dense, sparse, nscores, out + O_AFF);

    /* main stream: fps (1 block per batch, two barriers, tree rescan) */
    fps_kernel<<<B_BATCH, TFPS, SM_TOTAL>>>(seed_xyz, graspness);

    vmax_kernel<<<(B_BATCH*NS*3*32 + 255)/256, 256, 0, s2>>>(appr);
    scatter_kernel<<<(B_BATCH*NS + 255)/256, 256, 0, s2>>>(sparse, nviewsc, ngraspsc,
                                                           out + O_VIEW, out + O_GRASP);
    cudaEventRecord(e2, s2);

    gather_kernel<<<dim3(MPTS, B_BATCH), CDIM>>>(seed_xyz, seed_feat,
                                                 out + O_XYZ, out + O_FEAT);
    /* join */
    cudaStreamWaitEvent(0, e2, 0);
    (void)in_sizes; (void)n_in; (void)out_size;
}

// round 16
// speedup vs baseline: 4.2584x; 1.0168x over previous
#include <cuda_runtime.h>
#include <math.h>
#include <stdint.h>

#define B_BATCH 2
#define NPTS    20480
#define MPTS    2048
#define CDIM    256
#define ND      16384
#define NS      512
#define NVIEW   800
#define GTH     0.001f

#define TFPS    256
#define PMAX    44                /* points per thread (fast path) */
#define NPAIR   (PMAX/2)          /* 22 f32x2 pairs                */
#define NVMAX   (TFPS*PMAX)       /* 11264 compacted-point capacity */

/* output offsets (floats), concatenated in reference return order */
#define O_XYZ   0
#define O_FEAT  (B_BATCH*MPTS*3)                    /* 12288    */
#define O_AFF   (O_FEAT + B_BATCH*MPTS*CDIM)        /* 1060864  */
#define O_VIEW  (O_AFF + B_BATCH*ND)                /* 1093632  */
#define O_GRASP (O_VIEW + B_BATCH*NS*NVIEW)         /* 1912832  */

/* fps smem layout (bytes) */
#define SM_PS    0                          /* float4 ps[NVMAX] (180224B) */
#define SM_WIN   (SM_PS + NVMAX*16)         /* int win[MPTS]    (8192B)   */
#define SM_SCAN  (SM_WIN + MPTS*4)          /* int scan[TFPS]   (1024B)   */
#define SM_AUX   (SM_SCAN + TFPS*4)         /* redW[8] + bciA[2] + pad    */
#define SM_TOTAL (SM_AUX + 16*4)

typedef unsigned long long ull;

__device__ float g_views[NVIEW*3];
__device__ int   g_oi[B_BATCH*NPTS];     /* compacted -> original index */
__device__ float g_cc[B_BATCH*NPTS*3];   /* fallback compacted coords   */
__device__ int   g_fps[B_BATCH*MPTS];    /* FPS-selected original idx   */
__device__ int   g_vind[B_BATCH*NS*3];   /* per-approach best view      */

/* ---------- packed f32x2 helpers (per-lane identical to scalar .rn) ---------- */
__device__ __forceinline__ ull pk2(float a, float b){
    ull r; asm("mov.b64 %0, {%1,%2};" : "=l"(r) : "f"(a), "f"(b)); return r;
}
__device__ __forceinline__ void upk2(ull v, float &a, float &b){
    asm("mov.b64 {%0,%1}, %2;" : "=f"(a), "=f"(b) : "l"(v));
}
__device__ __forceinline__ ull add2(ull a, ull b){
    ull r; asm("add.rn.f32x2 %0, %1, %2;" : "=l"(r) : "l"(a), "l"(b)); return r;
}
__device__ __forceinline__ ull mul2(ull a, ull b){
    ull r; asm("mul.rn.f32x2 %0, %1, %2;" : "=l"(r) : "l"(a), "l"(b)); return r;
}

/* ---------- view templates: fp64 Fibonacci sphere, matches numpy ---------- */
__global__ void views_kernel(){
    const double phi = (sqrt(5.0) - 1.0) * 0.5;
    for (int i = threadIdx.x; i < NVIEW; i += blockDim.x){
        double zi = (2.0 * (double)i + 1.0) / (double)NVIEW - 1.0;
        double r2 = 1.0 - zi * zi; if (r2 < 0.0) r2 = 0.0;
        double r  = sqrt(r2);
        double ang = 2.0 * 3.141592653589793 * (double)i * phi;
        g_views[i*3+0] = (float)(r * cos(ang));
        g_views[i*3+1] = (float)(r * sin(ang));
        g_views[i*3+2] = (float)zi;
    }
}

/* ---------- zero-fill the scatter outputs (128-bit stores) ---------- */
__global__ void zero_kernel(float4* __restrict__ p, size_t n4){
    size_t stride = (size_t)gridDim.x * blockDim.x;
    for (size_t i = (size_t)blockIdx.x * blockDim.x + threadIdx.x; i < n4; i += stride)
        p[i] = make_float4(0.f, 0.f, 0.f, 0.f);
}

/* ---------- generic block argmax for 8 warps (fallback path only) ---------- */
__device__ __forceinline__ int block_argmax8(float bestd, int bestc,
                                             float* redD, int* redC, int* bci, int t){
    #pragma unroll
    for (int off = 16; off > 0; off >>= 1){
        float od = __shfl_down_sync(0xffffffffu, bestd, off);
        int   oc = __shfl_down_sync(0xffffffffu, bestc, off);
        if (od > bestd || (od == bestd && oc < bestc)){ bestd = od; bestc = oc; }
    }
    if ((t & 31) == 0){ redD[t>>5] = bestd; redC[t>>5] = bestc; }
    __syncthreads();
    if (t < 32){
        float bd  = (t < 8) ? redD[t] : -3.3e38f;
        int   bcv = (t < 8) ? redC[t] : 0x7fffffff;
        #pragma unroll
        for (int off = 4; off > 0; off >>= 1){
            float od = __shfl_down_sync(0xffffffffu, bd, off);
            int   oc = __shfl_down_sync(0xffffffffu, bcv, off);
            if (od > bd || (od == bd && oc < bcv)){ bd = od; bcv = oc; }
        }
        if (t == 0) *bci = bcv;
    }
    __syncthreads();
    return *bci;
}

/* ---------- masked FPS, one block per batch (champion structure) ---------- */
__global__ void __launch_bounds__(TFPS, 1)
fps_kernel(const float* __restrict__ xyz, const float* __restrict__ gsc){
    extern __shared__ unsigned char fsm[];
    const int b = blockIdx.x;
    const int t = threadIdx.x;
    const int lane = t & 31;
    const int w = t >> 5;
    const float* X = xyz + (size_t)b * NPTS * 3;
    const float* G = gsc + (size_t)b * NPTS;

    float4*   ps   = (float4*)(fsm + SM_PS);
    int*      win  = (int*)(fsm + SM_WIN);
    int*      scan = (int*)(fsm + SM_SCAN);
    unsigned* redW = (unsigned*)(fsm + SM_AUX);    /* [8]  */
    int*      bciA = (int*)(fsm + SM_AUX) + 8;     /* [2]  */

    /* ---- order-preserving compaction of graspable points ---- */
    const int CH = NPTS / TFPS;  /* 80 */
    int base = t * CH;
    int cnt = 0;
    for (int j = 0; j < CH; j++) cnt += (G[base + j] > GTH) ? 1 : 0;
    scan[t] = cnt;
    __syncthreads();
    for (int off = 1; off < TFPS; off <<= 1){
        int v = scan[t];
        int a = (t >= off) ? scan[t - off] : 0;
        __syncthreads();
        scan[t] = v + a;
        __syncthreads();
    }
    int Nv  = scan[TFPS - 1];
    int pos = scan[t] - cnt;
    bool fast = (Nv <= NVMAX);
    for (int j = 0; j < CH; j++){
        int idx = base + j;
        if (G[idx] > GTH){
            float x = X[idx*3+0], y = X[idx*3+1], z = X[idx*3+2];
            if (fast){
                ps[pos] = make_float4(x, y, z, 0.f);
            } else {
                size_t gp = ((size_t)b * NPTS + pos) * 3;
                g_cc[gp] = x; g_cc[gp+1] = y; g_cc[gp+2] = z;
            }
            g_oi[b*NPTS + pos] = idx;
            pos++;
        }
    }
    if (t == 0){ bciA[0] = 0x7fffffff; bciA[1] = 0x7fffffff; win[0] = 0; }
    __syncthreads();

    if (Nv <= 0){
        for (int m = t; m < MPTS; m += TFPS) g_fps[b*MPTS + m] = 0;
        return;
    }

    if (!fast){
        /* fallback (statistically unreachable): dists in smem, coords global */
        float* dst  = (float*)ps;          /* ps region: room for NPTS floats */
        float* redD = (float*)scan;
        int*   redC = (int*)(redD + 8);
        int*   bci  = redC + 8;
        for (int c = t; c < Nv; c += TFPS) dst[c] = 1e10f;
        if (t == 0) g_fps[b*MPTS] = g_oi[b*NPTS];
        __syncthreads();
        float px = g_cc[(size_t)b*NPTS*3+0];
        float py = g_cc[(size_t)b*NPTS*3+1];
        float pz = g_cc[(size_t)b*NPTS*3+2];
        for (int m = 1; m < MPTS; m++){
            float bestd = -1.0f; int bestc = 0x7fffffff;
            for (int c = t; c < Nv; c += TFPS){
                const float* P = &g_cc[((size_t)b*NPTS + c)*3];
                float dx = __fadd_rn(P[0], -px);
                float dy = __fadd_rn(P[1], -py);
                float dz = __fadd_rn(P[2], -pz);
                float d  = __fadd_rn(__fadd_rn(__fmul_rn(dx,dx), __fmul_rn(dy,dy)),
                                     __fmul_rn(dz,dz));
                float nd = fminf(dst[c], d);
                dst[c] = nd;
                if (nd > bestd){ bestd = nd; bestc = c; }
            }
            int wc = block_argmax8(bestd, bestc, redD, redC, bci, t);
            if (t == 0) g_fps[b*MPTS + m] = g_oi[b*NPTS + wc];
            const float* P = &g_cc[((size_t)b*NPTS + wc)*3];
            px = P[0]; py = P[1]; pz = P[2];
            __syncthreads();
        }
        return;
    }

    /* ================= fast path ================= */
    /* register-resident points; pads mirror slot 0 (distance mirrors slot 0;
       at the argmax, slot 0 itself also matches and wins the atomicMin)     */
    ull Xp[NPAIR], Yp[NPAIR], Zp[NPAIR];
    unsigned Du[PMAX];
    #pragma unroll
    for (int p = 0; p < NPAIR; p++){
        int c0 = t + (2*p) * TFPS;
        int c1 = c0 + TFPS;
        float4 P0 = ps[(c0 < Nv) ? c0 : 0];
        float4 P1 = ps[(c1 < Nv) ? c1 : 0];
        Xp[p] = pk2(P0.x, P1.x);
        Yp[p] = pk2(P0.y, P1.y);
        Zp[p] = pk2(P0.z, P1.z);
        Du[2*p] = __float_as_uint(1e10f); Du[2*p+1] = __float_as_uint(1e10f);
    }
    float4 P0v = ps[0];
    float px = P0v.x, py = P0v.y, pz = P0v.z;
    int par = 0;

    for (int m = 1; m < MPTS; m++){
        /* ---- region A: distance updates + local max tree ---- */
        ull nx = pk2(-px, -px), ny = pk2(-py, -py), nz = pk2(-pz, -pz);
        unsigned v[NPAIR];
        #pragma unroll
        for (int p = 0; p < NPAIR; p++){
            ull dx = add2(Xp[p], nx);               /* x - px */
            ull dy = add2(Yp[p], ny);
            ull dz = add2(Zp[p], nz);
            ull s  = add2(add2(mul2(dx,dx), mul2(dy,dy)), mul2(dz,dz));
            float d0, d1; upk2(s, d0, d1);
            unsigned n0 = min(Du[2*p],   __float_as_uint(d0));
            unsigned n1 = min(Du[2*p+1], __float_as_uint(d1));
            Du[2*p] = n0; Du[2*p+1] = n1;
            v[p] = max(n0, n1);
        }
        /* 22 -> 1 max tree, depth 5, compile-time indices */
        #pragma unroll
        for (int i = 0; i < 11; i++) v[i] = max(v[i], v[i+11]);
        #pragma unroll
        for (int i = 0; i < 5; i++)  v[i] = max(v[i], v[i+6]);
        #pragma unroll
        for (int i = 0; i < 3; i++)  v[i] = max(v[i], v[i+3]);
        unsigned localmax = max(max(v[0], v[1]), v[2]);

        unsigned wmax = __reduce_max_sync(0xffffffffu, localmax);
        if (lane == 0) redW[w] = wmax;
        __syncthreads();  /* bar1 */

        /* ---- block max, winner rescan, reset other slot ---- */
        unsigned rv = (lane < 8) ? redW[lane] : 0u;
        unsigned bmax = __reduce_max_sync(0xffffffffu, rv);
        if (t == 0) bciA[par ^ 1] = 0x7fffffff;   /* independent; issues early */
        if (localmax == bmax){
            int c = 0x7fffffff;
            #pragma unroll
            for (int i = 0; i < PMAX; i++)
                if (Du[i] == bmax) c = min(c, t + i*TFPS);
            atomicMin(&bciA[par], c);
        }
        __syncthreads();  /* bar2 */

        int wc = bciA[par];
        if (t == 0) win[m] = wc;          /* STS only: no global on the loop path */
        float4 P = ps[wc];
        px = P.x; py = P.y; pz = P.z;
        par ^= 1;
    }

    /* ---- deferred slot -> original-index translation ---- */
    __syncthreads();
    for (int m = t; m < MPTS; m += TFPS)
        g_fps[b*MPTS + m] = g_oi[b*NPTS + win[m]];
}

/* ---------- gather xyz + features by FPS indices ---------- */
__global__ void gather_kernel(const float* __restrict__ xyz, const float* __restrict__ feat,
                              float* __restrict__ oxyz, float* __restrict__ ofeat){
    int m = blockIdx.x, b = blockIdx.y;
    int j = g_fps[b*MPTS + m];
    int c = threadIdx.x;
    ofeat[((size_t)(b*MPTS + m))*CDIM + c] = feat[((size_t)b*NPTS + j)*CDIM + c];
    if (c < 3)
        oxyz[((size_t)(b*MPTS + m))*3 + c] = xyz[((size_t)b*NPTS + j)*3 + c];
}

/* ---------- stage 2: 2-NN affordance (d2 = sn + sq - 2*dot, as written) ---------- */
__global__ void nn_kernel(const float* __restrict__ dense, const float* __restrict__ sparse,
                          const float* __restrict__ scores, float* __restrict__ aff){
    __shared__ float sx[NS], sy[NS], sz[NS], sq[NS], sc[NS];
    __shared__ unsigned char sv[NS];
    int b = blockIdx.y;
    for (int i = threadIdx.x; i < NS; i += blockDim.x){
        float x = sparse[((size_t)b*NS + i)*3+0];
        float y = sparse[((size_t)b*NS + i)*3+1];
        float z = sparse[((size_t)b*NS + i)*3+2];
        sx[i]=x; sy[i]=y; sz[i]=z;
        sq[i] = __fadd_rn(__fadd_rn(__fmul_rn(x,x), __fmul_rn(y,y)), __fmul_rn(z,z));
        sv[i] = (x != 0.f || y != 0.f || z != 0.f) ? 1 : 0;
        sc[i] = scores[b*NS + i];
    }
    __syncthreads();
    int j = blockIdx.x * blockDim.x + threadIdx.x;
    float x = dense[((size_t)b*ND + j)*3+0];
    float y = dense[((size_t)b*ND + j)*3+1];
    float z = dense[((size_t)b*ND + j)*3+2];
    float sn = __fadd_rn(__fadd_rn(__fmul_rn(x,x), __fmul_rn(y,y)), __fmul_rn(z,z));
    float d1 = 3.3e38f, d2 = 3.3e38f; int i1 = 0, i2 = 0;
    for (int i = 0; i < NS; i++){
        float dot = __fadd_rn(__fadd_rn(__fmul_rn(x,sx[i]), __fmul_rn(y,sy[i])),
                              __fmul_rn(z,sz[i]));
        float dd  = sv[i] ? __fadd_rn(__fadd_rn(sn, sq[i]), __fmul_rn(-2.0f, dot)) : 1e10f;
        if (dd < d1){ d2 = d1; i2 = i1; d1 = dd; i1 = i; }
        else if (dd < d2){ d2 = dd; i2 = i; }
    }
    aff[b*ND + j] = __fmul_rn(__fadd_rn(sc[i1], sc[i2]), 0.5f);
}

/* ---------- stage 3a: best view per approach dir (argmax dot, tie->first) ---------- */
__global__ void vmax_kernel(const float* __restrict__ appr){
    int gtid = blockIdx.x * blockDim.x + threadIdx.x;
    int wid  = gtid >> 5;
    int lane = gtid & 31;
    if (wid >= B_BATCH*NS*3) return;
    const float* a = appr + (size_t)wid * 3;
    float ax = a[0], ay = a[1], az = a[2];
    float bm = -3.3e38f; int bv = 0x7fffffff;
    for (int v = lane; v < NVIEW; v += 32){
        float d = __fadd_rn(__fadd_rn(__fmul_rn(ax, g_views[v*3+0]),
                                      __fmul_rn(ay, g_views[v*3+1])),
                            __fmul_rn(az, g_views[v*3+2]));
        if (d > bm){ bm = d; bv = v; }
    }
    #pragma unroll
    for (int off = 16; off > 0; off >>= 1){
        float od = __shfl_down_sync(0xffffffffu, bm, off);
        int   ov = __shfl_down_sync(0xffffffffu, bv, off);
        if (od > bm || (od == bm && ov < bv)){ bm = od; bv = ov; }
    }
    if (lane == 0) g_vind[wid] = bv;
}

/* ---------- stage 3b: scatter (one thread per (b,n); k ascending -> last wins) ---------- */
__global__ void scatter_kernel(const float* __restrict__ sparse,
                               const float* __restrict__ nvs,
                               const float* __restrict__ ngs,
                               float* __restrict__ vs_out,
                               float* __restrict__ gs_out){
    int idx = blockIdx.x * blockDim.x + threadIdx.x;   /* b*NS + n */
    if (idx >= B_BATCH*NS) return;
    const float* sp = sparse + (size_t)idx * 3;
    float vm = (sp[0] != 0.f || sp[1] != 0.f || sp[2] != 0.f) ? 1.f : 0.f;
    for (int k = 0; k < 3; k++){
        int v = g_vind[idx*3 + k];
        vs_out[(size_t)idx*NVIEW + v] = __fmul_rn(nvs[idx*3 + k], vm);
        const float* src = ngs + ((size_t)(idx*3 + k)) * 84;
        float* dst = gs_out + ((size_t)idx*NVIEW + v) * 84;
        for (int j = 0; j < 84; j++) dst[j] = __fmul_rn(src[j], vm);
    }
}

extern "C" void kernel_launch(void* const* d_in, const int* in_sizes, int n_in,
                              void* d_out, int out_size){
    const float* seed_xyz   = (const float*)d_in[0];
    const float* seed_feat  = (const float*)d_in[1];
    const float* graspness  = (const float*)d_in[2];
    const float* dense      = (const float*)d_in[3];
    const float* sparse     = (const float*)d_in[4];
    const float* nscores    = (const float*)d_in[5];
    const float* appr       = (const float*)d_in[6];
    const float* nviewsc    = (const float*)d_in[7];
    const float* ngraspsc   = (const float*)d_in[8];
    float* out = (float*)d_out;

    static cudaStream_t s2;
    static cudaEvent_t  e1, e2;
    static int init_done = 0;
    if (!init_done){
        cudaStreamCreateWithFlags(&s2, cudaStreamNonBlocking);
        cudaEventCreateWithFlags(&e1, cudaEventDisableTiming);
        cudaEventCreateWithFlags(&e2, cudaEventDisableTiming);
        cudaFuncSetAttribute(fps_kernel, cudaFuncAttributeMaxDynamicSharedMemorySize,
                             SM_TOTAL);
        init_done = 1;
    }

    /* fork side stream (graph-capturable fork/join pattern) */
    cudaEventRecord(e1, 0);
    cudaStreamWaitEvent(s2, e1, 0);

    /* side stream: everything independent of FPS (overlaps the long fps kernel) */
    {
        size_t n4 = (size_t)(B_BATCH*NS*NVIEW + B_BATCH*NS*NVIEW*84) / 4;
        zero_kernel<<<2048, 256, 0, s2>>>((float4*)(out + O_VIEW), n4);
    }
    views_kernel<<<1, 256, 0, s2>>>();
    nn_kernel<<<dim3(ND/256, B_BATCH), 256, 0, s2>>>(dense, sparse, nscores, out + O_AFF);

    /* main stream: fps (1 block per batch, champion structure) */
    fps_kernel<<<B_BATCH, TFPS, SM_TOTAL>>>(seed_xyz, graspness);

    vmax_kernel<<<(B_BATCH*NS*3*32 + 255)/256, 256, 0, s2>>>(appr);
    scatter_kernel<<<(B_BATCH*NS + 255)/256, 256, 0, s2>>>(sparse, nviewsc, ngraspsc,
                                                           out + O_VIEW, out + O_GRASP);
    cudaEventRecord(e2, s2);

    gather_kernel<<<dim3(MPTS, B_BATCH), CDIM>>>(seed_xyz, seed_feat,
                                                 out + O_XYZ, out + O_FEAT);
    /* join */
    cudaStreamWaitEvent(0, e2, 0);
    (void)in_sizes; (void)n_in; (void)out_size;
}